// round 2
// baseline (speedup 1.0000x reference)
#include <cuda_runtime.h>

// Problem dims (fixed by setup_inputs)
constexpr int Bd = 4;
constexpr int Sd = 2048;
constexpr int Ed = 1024;
constexpr float SCALE_F = 0.125f;

constexpr long ME = (long)Ed * Ed;          // 1M elems per E x E matrix
constexpr long MAT_SLOT = (long)Bd * ME;    // 4M elems per per-batch matrix group

// Scratch: G, H, M, T, U  (each Bd x E x E) + vectors (s, p, r, e, c : Bd x E each)
__device__ float g_scratch[5 * 4 * 1024 * 1024 + 5 * 4 * 1024];

// ---------------------------------------------------------------------------
// coldot: y[j] = sum_i A[i*ldr + j] * (w ? w[i] : 1)
// ---------------------------------------------------------------------------
__global__ void coldot_k(const float* __restrict__ A, long sA,
                         const float* __restrict__ w,
                         float* __restrict__ y, int sy,
                         int rows, int ldr)
{
    A += (long)blockIdx.y * sA;
    y += blockIdx.y * sy;
    int j = blockIdx.x * blockDim.x + threadIdx.x;
    float acc = 0.f;
#pragma unroll 8
    for (int i = 0; i < rows; i++) {
        float wv = w ? w[i] : 1.f;
        acc += A[(long)i * ldr + j] * wv;
    }
    y[j] = acc;
}

// ---------------------------------------------------------------------------
// rowdot: y[i] = alpha * dot(A[i,:], xv) + (bias ? bias[i] : 0)
// one warp per output row
// ---------------------------------------------------------------------------
__global__ void rowdot_k(const float* __restrict__ A,
                         const float* __restrict__ xv, int sxv,
                         const float* __restrict__ bias,
                         float* __restrict__ y, int sy,
                         int cols, float alpha)
{
    xv += blockIdx.y * sxv;
    y  += blockIdx.y * sy;
    int warp = blockIdx.x * (blockDim.x >> 5) + (threadIdx.x >> 5);
    int lane = threadIdx.x & 31;
    const float* row = A + (long)warp * cols;
    float acc = 0.f;
    for (int j = lane; j < cols; j += 32) acc += row[j] * xv[j];
#pragma unroll
    for (int o = 16; o > 0; o >>= 1) acc += __shfl_xor_sync(0xffffffffu, acc, o);
    if (lane == 0) y[warp] = alpha * acc + (bias ? bias[warp] : 0.f);
}

// ---------------------------------------------------------------------------
// Tiled fp32 GEMM:  C = alpha * op(A) op(B)  [+ epilogue]
//   TA: op(A)[m,k] stored at A[k*Md + m]  (else A[m*Kd + k])
//   TB: op(B)[k,n] stored at B[n*Kd + k]  (else B[k*Nd + n])
//   mode 1: C += v1[m]*v2[n] + v3[m]*(v4[n] + rk*v2[n])   (rank-1 corrections)
//   mode 2: C += v1[n]                                     (row-vector bias)
// All dims multiples of 128 (K multiple of 16): no bounds checks.
// ---------------------------------------------------------------------------
constexpr int BM = 128, BN = 128, BK = 16;

template <bool TA, bool TB>
__global__ void __launch_bounds__(256, 2) gemm_k(
    const float* __restrict__ A, const float* __restrict__ B,
    float* __restrict__ C,
    int Md, int Nd, int Kd,
    long sA, long sB, long sC,
    float alpha, int mode,
    const float* __restrict__ v1, int sv1,
    const float* __restrict__ v2,
    const float* __restrict__ v3,
    const float* __restrict__ v4, int sv4,
    float rk)
{
    int bz = blockIdx.z;
    A += (long)bz * sA;
    B += (long)bz * sB;
    C += (long)bz * sC;
    if (v1) v1 += bz * sv1;
    if (v4) v4 += bz * sv4;

    const int m0 = blockIdx.y * BM;
    const int n0 = blockIdx.x * BN;
    const int lda = TA ? Md : Kd;
    const int ldb = TB ? Kd : Nd;
    const int ldc = Nd;

    __shared__ float As[BK][BM + 4];
    __shared__ float Bs[BK][BN + 4];

    const int tid = threadIdx.x;
    const int tx = tid & 15;
    const int ty = tid >> 4;

    float acc[8][8];
#pragma unroll
    for (int i = 0; i < 8; i++)
#pragma unroll
        for (int j = 0; j < 8; j++) acc[i][j] = 0.f;

    for (int k0 = 0; k0 < Kd; k0 += BK) {
#pragma unroll
        for (int l = 0; l < 2; l++) {
            int f = tid + l * 256;
            if (TA) {
                int k = f >> 5, m4 = (f & 31) << 2;
                float4 v = *(const float4*)&A[(long)(k0 + k) * lda + m0 + m4];
                As[k][m4 + 0] = v.x; As[k][m4 + 1] = v.y;
                As[k][m4 + 2] = v.z; As[k][m4 + 3] = v.w;
            } else {
                int m = f >> 2, kq = (f & 3) << 2;
                float4 v = *(const float4*)&A[(long)(m0 + m) * lda + k0 + kq];
                As[kq + 0][m] = v.x; As[kq + 1][m] = v.y;
                As[kq + 2][m] = v.z; As[kq + 3][m] = v.w;
            }
            if (!TB) {
                int k = f >> 5, n4 = (f & 31) << 2;
                float4 v = *(const float4*)&B[(long)(k0 + k) * ldb + n0 + n4];
                Bs[k][n4 + 0] = v.x; Bs[k][n4 + 1] = v.y;
                Bs[k][n4 + 2] = v.z; Bs[k][n4 + 3] = v.w;
            } else {
                int n = f >> 2, kq = (f & 3) << 2;
                float4 v = *(const float4*)&B[(long)(n0 + n) * ldb + k0 + kq];
                Bs[kq + 0][n] = v.x; Bs[kq + 1][n] = v.y;
                Bs[kq + 2][n] = v.z; Bs[kq + 3][n] = v.w;
            }
        }
        __syncthreads();
#pragma unroll
        for (int k = 0; k < BK; k++) {
            float a[8], b[8];
#pragma unroll
            for (int i = 0; i < 4; i++) {
                a[i]     = As[k][ty * 4 + i];
                a[4 + i] = As[k][64 + ty * 4 + i];
                b[i]     = Bs[k][tx * 4 + i];
                b[4 + i] = Bs[k][64 + tx * 4 + i];
            }
#pragma unroll
            for (int i = 0; i < 8; i++)
#pragma unroll
                for (int j = 0; j < 8; j++) acc[i][j] += a[i] * b[j];
        }
        __syncthreads();
    }

#pragma unroll
    for (int i = 0; i < 8; i++) {
        int m = m0 + ((i < 4) ? ty * 4 + i : 64 + ty * 4 + (i - 4));
        float pv = 0.f, bkv = 0.f;
        if (mode == 1) { pv = v1[m]; bkv = v3[m]; }
#pragma unroll
        for (int j = 0; j < 8; j++) {
            int n = n0 + ((j < 4) ? tx * 4 + j : 64 + tx * 4 + (j - 4));
            float val = alpha * acc[i][j];
            if (mode == 1)      val += pv * v2[n] + bkv * (v4[n] + rk * v2[n]);
            else if (mode == 2) val += v1[n];
            C[(long)m * ldc + n] = val;
        }
    }
}

// ---------------------------------------------------------------------------
// Launch: out = scale * x (Wq^T (K^T V) Wo^T) + row_bias   via
//   G = x^T x ; M = Wk G Wv^T + rank1(bias terms) ; T = M Wo^T ; U = Wq^T T
//   c = scale * Wo (M^T bq) + bo ; out = scale * x U + c
// ---------------------------------------------------------------------------
extern "C" void kernel_launch(void* const* d_in, const int* in_sizes, int n_in,
                              void* d_out, int out_size)
{
    const float* x  = (const float*)d_in[0];
    const float* Wq = (const float*)d_in[1];
    const float* bq = (const float*)d_in[2];
    const float* Wk = (const float*)d_in[3];
    const float* bk = (const float*)d_in[4];
    const float* Wv = (const float*)d_in[5];
    const float* bv = (const float*)d_in[6];
    const float* Wo = (const float*)d_in[7];
    const float* bo = (const float*)d_in[8];
    float* out = (float*)d_out;

    float* scr = nullptr;
    cudaGetSymbolAddress((void**)&scr, g_scratch);

    float* G  = scr + 0 * MAT_SLOT;
    float* H  = scr + 1 * MAT_SLOT;
    float* Mm = scr + 2 * MAT_SLOT;
    float* T  = scr + 3 * MAT_SLOT;
    float* U  = scr + 4 * MAT_SLOT;
    float* vec = scr + 5 * MAT_SLOT;
    float* s = vec + 0 * (Bd * Ed);
    float* p = vec + 1 * (Bd * Ed);
    float* r = vec + 2 * (Bd * Ed);
    float* e = vec + 3 * (Bd * Ed);
    float* c = vec + 4 * (Bd * Ed);

    const long sX = (long)Sd * Ed;   // per-batch stride of x / out
    const long sM = ME;              // per-batch stride of E x E scratch

    dim3 blk(256);
    dim3 grd_ee(Ed / BN, Ed / BM, Bd);   // (8,8,4)
    dim3 grd_se(Ed / BN, Sd / BM, Bd);   // (8,16,4)

    // 1. s_b = colsum(x_b)
    coldot_k<<<dim3(Ed / 256, Bd), 256>>>(x, sX, nullptr, s, Ed, Sd, Ed);

    // 2. G_b = x_b^T x_b
    gemm_k<true, false><<<grd_ee, blk>>>(x, x, G, Ed, Ed, Sd, sX, sX, sM,
                                         1.f, 0, nullptr, 0, nullptr, nullptr, nullptr, 0, 0.f);

    // 3. p = Wk s ; r = Wv s
    rowdot_k<<<dim3(Ed / 8, Bd), 256>>>(Wk, s, Ed, nullptr, p, Ed, Ed, 1.f);
    rowdot_k<<<dim3(Ed / 8, Bd), 256>>>(Wv, s, Ed, nullptr, r, Ed, Ed, 1.f);

    // 4. H_b = Wk G_b
    gemm_k<false, false><<<grd_ee, blk>>>(Wk, G, H, Ed, Ed, Ed, 0, sM, sM,
                                          1.f, 0, nullptr, 0, nullptr, nullptr, nullptr, 0, 0.f);

    // 5. M_b = H_b Wv^T + p bv^T + bk r^T + S bk bv^T
    gemm_k<false, true><<<grd_ee, blk>>>(H, Wv, Mm, Ed, Ed, Ed, sM, 0, sM,
                                         1.f, 1, p, Ed, bv, bk, r, Ed, (float)Sd);

    // 6. e_b = M_b^T bq ; 7. c_b = SCALE * Wo e_b + bo
    coldot_k<<<dim3(Ed / 256, Bd), 256>>>(Mm, sM, bq, e, Ed, Ed, Ed);
    rowdot_k<<<dim3(Ed / 8, Bd), 256>>>(Wo, e, Ed, bo, c, Ed, Ed, SCALE_F);

    // 8. T_b = M_b Wo^T
    gemm_k<false, true><<<grd_ee, blk>>>(Mm, Wo, T, Ed, Ed, Ed, sM, 0, sM,
                                         1.f, 0, nullptr, 0, nullptr, nullptr, nullptr, 0, 0.f);

    // 9. U_b = Wq^T T_b
    gemm_k<true, false><<<grd_ee, blk>>>(Wq, T, U, Ed, Ed, Ed, 0, sM, sM,
                                         1.f, 0, nullptr, 0, nullptr, nullptr, nullptr, 0, 0.f);

    // 10. out_b = SCALE * x_b U_b + c_b
    gemm_k<false, false><<<grd_se, blk>>>(x, U, out, Sd, Ed, Ed, sX, sM, sX,
                                          SCALE_F, 2, c, Ed, nullptr, nullptr, nullptr, 0, 0.f);
}

// round 4
// speedup vs baseline: 2.1911x; 2.1911x over previous
#include <cuda_runtime.h>
#include <cuda_bf16.h>
#include <cstdint>
#include <cstring>

// Problem dims (fixed by setup_inputs)
constexpr int Bd = 4;
constexpr int Sd = 2048;
constexpr int Ed = 1024;
constexpr float SCALE_F = 0.125f;

constexpr long ME = (long)Ed * Ed;
constexpr long MAT_SLOT = (long)Bd * ME;

// Scratch: G, H, M, T, U (each Bd x E x E) + vectors (s, p, r, e, c : Bd x E each)
__device__ float g_scratch[5 * 4 * 1024 * 1024 + 5 * 4 * 1024];

// ===========================================================================
// helpers
// ===========================================================================
__device__ __forceinline__ uint32_t smem_u32(const void* p) {
    uint32_t a;
    asm("{ .reg .u64 t; cvta.to.shared.u64 t, %1; cvt.u32.u64 %0, t; }" : "=r"(a) : "l"(p));
    return a;
}
#define SWZ128(o) ((o) ^ (((o) >> 3) & 0x70))

__device__ __forceinline__ void split1(float v, float& h, float& l) {
    h = __bfloat162float(__float2bfloat16(v));
    l = v - h;
}
__device__ __forceinline__ uint32_t pack2(float a, float b) {
    __nv_bfloat16 ha = __float2bfloat16(a), hb = __float2bfloat16(b);
    uint16_t ua, ub;
    memcpy(&ua, &ha, 2); memcpy(&ub, &hb, 2);
    return (uint32_t)ua | ((uint32_t)ub << 16);
}

#define LDMX4(r0, r1, r2, r3, addr)                                            \
    asm volatile("ldmatrix.sync.aligned.m8n8.x4.shared.b16 {%0,%1,%2,%3}, [%4];" \
                 : "=r"(r0), "=r"(r1), "=r"(r2), "=r"(r3) : "r"(addr))

__device__ __forceinline__ void mma16816(float* c, const uint32_t* a, const uint32_t* b) {
    asm volatile(
        "mma.sync.aligned.m16n8k16.row.col.f32.bf16.bf16.f32 "
        "{%0,%1,%2,%3},{%4,%5,%6,%7},{%8,%9},{%0,%1,%2,%3};"
        : "+f"(c[0]), "+f"(c[1]), "+f"(c[2]), "+f"(c[3])
        : "r"(a[0]), "r"(a[1]), "r"(a[2]), "r"(a[3]), "r"(b[0]), "r"(b[1]));
}

// ===========================================================================
// small vector kernels
// ===========================================================================
__global__ void coldot_k(const float* __restrict__ A, long sA,
                         const float* __restrict__ w,
                         float* __restrict__ y, int sy, int rows, int ldr) {
    A += (long)blockIdx.y * sA;
    y += blockIdx.y * sy;
    int j = blockIdx.x * blockDim.x + threadIdx.x;
    float acc = 0.f;
#pragma unroll 8
    for (int i = 0; i < rows; i++) {
        float wv = w ? w[i] : 1.f;
        acc += A[(long)i * ldr + j] * wv;
    }
    y[j] = acc;
}

__global__ void rowdot_k(const float* __restrict__ A,
                         const float* __restrict__ xv, int sxv,
                         const float* __restrict__ bias,
                         float* __restrict__ y, int sy, int cols, float alpha) {
    xv += blockIdx.y * sxv;
    y  += blockIdx.y * sy;
    int warp = blockIdx.x * (blockDim.x >> 5) + (threadIdx.x >> 5);
    int lane = threadIdx.x & 31;
    const float* row = A + (long)warp * cols;
    float acc = 0.f;
    for (int j = lane; j < cols; j += 32) acc += row[j] * xv[j];
#pragma unroll
    for (int o = 16; o > 0; o >>= 1) acc += __shfl_xor_sync(0xffffffffu, acc, o);
    if (lane == 0) y[warp] = alpha * acc + (bias ? bias[warp] : 0.f);
}

// ===========================================================================
// mma.sync GEMM, fp32 via bf16 hi/lo split (3 products, fp32 accum)
//   C = alpha * op(A) op(B)  [+ epilogue]
//   TA : op(A)[m,k] = A[k*Md + m]   else A[m*Kd + k]
//   TBt: op(B)[k,n] = B[n*Kd + k]   else B[k*Nd + n]
//   mode 1: C += v1[m]*v2[n] + v3[m]*(v4[n] + rk*v2[n])
//   mode 2: C += v1[n]
// Block tile 128x128, K-chunk 64, 8 warps (warp tile 32x64), double-buffered.
// SMEM tile layout: [row][64 bf16] rows = m (A) / n (B), SW128 swizzle.
// ===========================================================================
constexpr int STAGE  = 65536;
constexpr int OFF_AH = 0;
constexpr int OFF_AL = 16384;
constexpr int OFF_BH = 32768;
constexpr int OFF_BL = 49152;
constexpr int DYN_SMEM = 2 * STAGE;  // 128 KB

// KMAJ: src[row][k], k contiguous (ld = row stride). else src[k][row], row contiguous.
// Loads half-chunk (k in [h*32, h*32+32)) into 16 regs.
template <bool KMAJ>
__device__ __forceinline__ void ldg_half(const float* __restrict__ src, long ld,
                                         int h, int tid, float* st) {
    if (KMAJ) {
#pragma unroll
        for (int i = 0; i < 4; i++) {
            int fid = tid + i * 256;
            int row = fid >> 3, c4 = fid & 7;
            float4 v = *(const float4*)(src + (long)row * ld + h * 32 + c4 * 4);
            st[i * 4 + 0] = v.x; st[i * 4 + 1] = v.y;
            st[i * 4 + 2] = v.z; st[i * 4 + 3] = v.w;
        }
    } else {
        int row = tid & 127, kg = tid >> 7;
        const float* s = src + (long)(h * 32 + kg * 16) * ld + row;
#pragma unroll
        for (int i = 0; i < 16; i++) st[i] = s[(long)i * ld];
    }
}

template <bool KMAJ>
__device__ __forceinline__ void sts_half(char* stg, int dh, int dl,
                                         int h, int tid, const float* st) {
    if (KMAJ) {
#pragma unroll
        for (int i = 0; i < 4; i++) {
            int fid = tid + i * 256;
            int row = fid >> 3, c4 = fid & 7;
            float h0, l0, h1, l1, h2, l2, h3, l3;
            split1(st[i * 4 + 0], h0, l0); split1(st[i * 4 + 1], h1, l1);
            split1(st[i * 4 + 2], h2, l2); split1(st[i * 4 + 3], h3, l3);
            uint32_t off = SWZ128((uint32_t)(row * 128 + h * 64 + c4 * 8));
            *(uint2*)(stg + dh + off) = make_uint2(pack2(h0, h1), pack2(h2, h3));
            *(uint2*)(stg + dl + off) = make_uint2(pack2(l0, l1), pack2(l2, l3));
        }
    } else {
        int row = tid & 127, kg = tid >> 7;
        uint32_t hi[8], lo[8];
#pragma unroll
        for (int i = 0; i < 8; i++) {
            float ha, la, hb, lb;
            split1(st[2 * i], ha, la);
            split1(st[2 * i + 1], hb, lb);
            hi[i] = pack2(ha, hb);
            lo[i] = pack2(la, lb);
        }
        uint32_t base = (uint32_t)(row * 128 + h * 64 + kg * 32);
#pragma unroll
        for (int u = 0; u < 2; u++) {
            uint32_t off = SWZ128(base + u * 16);
            *(uint4*)(stg + dh + off) = make_uint4(hi[u * 4], hi[u * 4 + 1], hi[u * 4 + 2], hi[u * 4 + 3]);
            *(uint4*)(stg + dl + off) = make_uint4(lo[u * 4], lo[u * 4 + 1], lo[u * 4 + 2], lo[u * 4 + 3]);
        }
    }
}

__device__ __forceinline__ void compute_ks(uint32_t sb, int ks, int m_warp, int n_warp,
                                           int lane, float (&acc)[2][8][4]) {
    const uint32_t rowsel = lane & 15;
    const uint32_t ksel = (lane >> 4) * 16;
    uint32_t ah[2][4], al[2][4];
#pragma unroll
    for (int mt = 0; mt < 2; mt++) {
        uint32_t off = SWZ128((uint32_t)((m_warp + mt * 16 + rowsel) * 128 + ks * 32 + ksel));
        LDMX4(ah[mt][0], ah[mt][1], ah[mt][2], ah[mt][3], sb + OFF_AH + off);
        LDMX4(al[mt][0], al[mt][1], al[mt][2], al[mt][3], sb + OFF_AL + off);
    }
    uint32_t bh[8][2], bl[8][2];
#pragma unroll
    for (int nt = 0; nt < 4; nt++) {
        uint32_t off = SWZ128((uint32_t)((n_warp + nt * 16 + rowsel) * 128 + ks * 32 + ksel));
        uint32_t r0, r1, r2, r3;
        LDMX4(r0, r1, r2, r3, sb + OFF_BH + off);
        bh[2 * nt][0] = r0; bh[2 * nt][1] = r2;
        bh[2 * nt + 1][0] = r1; bh[2 * nt + 1][1] = r3;
        LDMX4(r0, r1, r2, r3, sb + OFF_BL + off);
        bl[2 * nt][0] = r0; bl[2 * nt][1] = r2;
        bl[2 * nt + 1][0] = r1; bl[2 * nt + 1][1] = r3;
    }
#pragma unroll
    for (int mt = 0; mt < 2; mt++)
#pragma unroll
        for (int nf = 0; nf < 8; nf++) {
            mma16816(acc[mt][nf], ah[mt], bh[nf]);  // hi*hi
            mma16816(acc[mt][nf], ah[mt], bl[nf]);  // hi*lo
            mma16816(acc[mt][nf], al[mt], bh[nf]);  // lo*hi
        }
}

template <bool TA, bool TBt>
__global__ void __launch_bounds__(256, 1) mma_gemm(
    const float* __restrict__ A, const float* __restrict__ B, float* __restrict__ C,
    int Md, int Nd, int Kd, long sA, long sB, long sC,
    float alpha, int mode,
    const float* __restrict__ v1, int sv1, const float* __restrict__ v2,
    const float* __restrict__ v3, const float* __restrict__ v4, int sv4, float rk)
{
    extern __shared__ char smem[];
    const int bz = blockIdx.z;
    A += (long)bz * sA;
    B += (long)bz * sB;
    C += (long)bz * sC;
    if (v1) v1 += bz * sv1;
    if (v4) v4 += bz * sv4;

    const int m0 = blockIdx.y * 128;
    const int n0 = blockIdx.x * 128;
    const long lda = TA ? (long)Md : (long)Kd;
    const long ldb = TBt ? (long)Kd : (long)Nd;

    const int tid = threadIdx.x;
    const int wid = tid >> 5;
    const int lane = tid & 31;
    const int m_warp = (wid >> 1) * 32;
    const int n_warp = (wid & 1) * 64;
    const uint32_t sbase = smem_u32(smem);

    constexpr bool KA = !TA;
    constexpr bool KB = TBt;

    auto srcA = [&](int c) {
        return TA ? A + (long)(c * 64) * lda + m0 : A + (long)m0 * lda + c * 64;
    };
    auto srcB = [&](int c) {
        return TBt ? B + (long)n0 * ldb + c * 64 : B + (long)(c * 64) * ldb + n0;
    };

    float acc[2][8][4];
#pragma unroll
    for (int mt = 0; mt < 2; mt++)
#pragma unroll
        for (int nf = 0; nf < 8; nf++)
#pragma unroll
            for (int q = 0; q < 4; q++) acc[mt][nf][q] = 0.f;

    const int nCh = Kd / 64;

    // prologue: fill stage 0
    {
        float stA[16], stB[16];
#pragma unroll
        for (int h = 0; h < 2; h++) {
            ldg_half<KA>(srcA(0), lda, h, tid, stA);
            ldg_half<KB>(srcB(0), ldb, h, tid, stB);
            sts_half<KA>(smem, OFF_AH, OFF_AL, h, tid, stA);
            sts_half<KB>(smem, OFF_BH, OFF_BL, h, tid, stB);
        }
    }
    __syncthreads();

    for (int c = 0; c < nCh; c++) {
        const uint32_t sb = sbase + (c & 1) * STAGE;
        char* nx = smem + ((c + 1) & 1) * STAGE;
        const bool hn = (c + 1) < nCh;
        float stA[16], stB[16];
        if (hn) {
            ldg_half<KA>(srcA(c + 1), lda, 0, tid, stA);
            ldg_half<KB>(srcB(c + 1), ldb, 0, tid, stB);
        }
        compute_ks(sb, 0, m_warp, n_warp, lane, acc);
        compute_ks(sb, 1, m_warp, n_warp, lane, acc);
        if (hn) {
            sts_half<KA>(nx, OFF_AH, OFF_AL, 0, tid, stA);
            sts_half<KB>(nx, OFF_BH, OFF_BL, 0, tid, stB);
            ldg_half<KA>(srcA(c + 1), lda, 1, tid, stA);
            ldg_half<KB>(srcB(c + 1), ldb, 1, tid, stB);
        }
        compute_ks(sb, 2, m_warp, n_warp, lane, acc);
        compute_ks(sb, 3, m_warp, n_warp, lane, acc);
        if (hn) {
            sts_half<KA>(nx, OFF_AH, OFF_AL, 1, tid, stA);
            sts_half<KB>(nx, OFF_BH, OFF_BL, 1, tid, stB);
        }
        __syncthreads();
    }

    // epilogue
    const int r = lane >> 2;
    const int cp = (lane & 3) * 2;
#pragma unroll
    for (int mt = 0; mt < 2; mt++)
#pragma unroll
        for (int rr = 0; rr < 2; rr++) {
            const int m = m0 + m_warp + mt * 16 + r + rr * 8;
            float pv = 0.f, bkv = 0.f;
            if (mode == 1) { pv = v1[m]; bkv = v3[m]; }
            float* crow = C + (long)m * Nd + n0 + n_warp;
#pragma unroll
            for (int nf = 0; nf < 8; nf++) {
                const int nloc = nf * 8 + cp;
                const int n = n0 + n_warp + nloc;
                float f0 = alpha * acc[mt][nf][rr * 2 + 0];
                float f1 = alpha * acc[mt][nf][rr * 2 + 1];
                if (mode == 1) {
                    f0 += pv * v2[n + 0] + bkv * (v4[n + 0] + rk * v2[n + 0]);
                    f1 += pv * v2[n + 1] + bkv * (v4[n + 1] + rk * v2[n + 1]);
                } else if (mode == 2) {
                    f0 += v1[n + 0];
                    f1 += v1[n + 1];
                }
                *(float2*)(crow + nloc) = make_float2(f0, f1);
            }
        }
}

// ===========================================================================
// Launch: same 10-step factorization
//   G = x^T x ; M = Wk G Wv^T + rank1 ; T = M Wo^T ; U = Wq^T T
//   c = scale * Wo (M^T bq) + bo ; out = scale * x U + c
// ===========================================================================
extern "C" void kernel_launch(void* const* d_in, const int* in_sizes, int n_in,
                              void* d_out, int out_size)
{
    const float* x  = (const float*)d_in[0];
    const float* Wq = (const float*)d_in[1];
    const float* bq = (const float*)d_in[2];
    const float* Wk = (const float*)d_in[3];
    const float* bk = (const float*)d_in[4];
    const float* Wv = (const float*)d_in[5];
    const float* bv = (const float*)d_in[6];
    const float* Wo = (const float*)d_in[7];
    const float* bo = (const float*)d_in[8];
    float* out = (float*)d_out;

    float* scr = nullptr;
    cudaGetSymbolAddress((void**)&scr, g_scratch);

    float* G  = scr + 0 * MAT_SLOT;
    float* H  = scr + 1 * MAT_SLOT;
    float* Mm = scr + 2 * MAT_SLOT;
    float* T  = scr + 3 * MAT_SLOT;
    float* U  = scr + 4 * MAT_SLOT;
    float* vec = scr + 5 * MAT_SLOT;
    float* s = vec + 0 * (Bd * Ed);
    float* p = vec + 1 * (Bd * Ed);
    float* r = vec + 2 * (Bd * Ed);
    float* e = vec + 3 * (Bd * Ed);
    float* c = vec + 4 * (Bd * Ed);

    const long sX = (long)Sd * Ed;
    const long sM = ME;

    cudaFuncSetAttribute(mma_gemm<true,  false>, cudaFuncAttributeMaxDynamicSharedMemorySize, DYN_SMEM);
    cudaFuncSetAttribute(mma_gemm<false, false>, cudaFuncAttributeMaxDynamicSharedMemorySize, DYN_SMEM);
    cudaFuncSetAttribute(mma_gemm<false, true >, cudaFuncAttributeMaxDynamicSharedMemorySize, DYN_SMEM);

    dim3 blk(256);
    dim3 grd_ee(Ed / 128, Ed / 128, Bd);   // (8,8,4)
    dim3 grd_se(Ed / 128, Sd / 128, Bd);   // (8,16,4)

    // 1. s_b = colsum(x_b)
    coldot_k<<<dim3(Ed / 256, Bd), 256>>>(x, sX, nullptr, s, Ed, Sd, Ed);

    // 2. G_b = x_b^T x_b
    mma_gemm<true, false><<<grd_ee, blk, DYN_SMEM>>>(x, x, G, Ed, Ed, Sd, sX, sX, sM,
        1.f, 0, nullptr, 0, nullptr, nullptr, nullptr, 0, 0.f);

    // 3. p = Wk s ; r = Wv s
    rowdot_k<<<dim3(Ed / 8, Bd), 256>>>(Wk, s, Ed, nullptr, p, Ed, Ed, 1.f);
    rowdot_k<<<dim3(Ed / 8, Bd), 256>>>(Wv, s, Ed, nullptr, r, Ed, Ed, 1.f);

    // 4. H_b = Wk G_b
    mma_gemm<false, false><<<grd_ee, blk, DYN_SMEM>>>(Wk, G, H, Ed, Ed, Ed, 0, sM, sM,
        1.f, 0, nullptr, 0, nullptr, nullptr, nullptr, 0, 0.f);

    // 5. M_b = H_b Wv^T + p bv^T + bk r^T + S bk bv^T
    mma_gemm<false, true><<<grd_ee, blk, DYN_SMEM>>>(H, Wv, Mm, Ed, Ed, Ed, sM, 0, sM,
        1.f, 1, p, Ed, bv, bk, r, Ed, (float)Sd);

    // 6. e_b = M_b^T bq ; 7. c_b = SCALE * Wo e_b + bo
    coldot_k<<<dim3(Ed / 256, Bd), 256>>>(Mm, sM, bq, e, Ed, Ed, Ed);
    rowdot_k<<<dim3(Ed / 8, Bd), 256>>>(Wo, e, Ed, bo, c, Ed, Ed, SCALE_F);

    // 8. T_b = M_b Wo^T
    mma_gemm<false, true><<<grd_ee, blk, DYN_SMEM>>>(Mm, Wo, T, Ed, Ed, Ed, sM, 0, sM,
        1.f, 0, nullptr, 0, nullptr, nullptr, nullptr, 0, 0.f);

    // 9. U_b = Wq^T T_b
    mma_gemm<true, false><<<grd_ee, blk, DYN_SMEM>>>(Wq, T, U, Ed, Ed, Ed, 0, sM, sM,
        1.f, 0, nullptr, 0, nullptr, nullptr, nullptr, 0, 0.f);

    // 10. out_b = SCALE * x_b U_b + c_b
    mma_gemm<false, false><<<grd_se, blk, DYN_SMEM>>>(x, U, out, Sd, Ed, Ed, sX, sM, sX,
        SCALE_F, 2, c, Ed, nullptr, nullptr, nullptr, 0, 0.f);
}

// round 5
// speedup vs baseline: 2.9956x; 1.3672x over previous
#include <cuda_runtime.h>
#include <cuda_bf16.h>
#include <cstdint>
#include <cstring>

// Problem dims (fixed by setup_inputs)
constexpr int Bd = 4;
constexpr int Sd = 2048;
constexpr int Ed = 1024;
constexpr float SCALE_F = 0.125f;

// ===========================================================================
// scratch layout (bytes)
// ===========================================================================
constexpr long MB = 1024 * 1024;
constexpr long OFF_XS_H = 0;          // x split      [B][S][E] bf16  16MB
constexpr long OFF_XS_L = 16 * MB;
constexpr long OFF_XT_H = 32 * MB;    // x^T split    [B][E][S] bf16  16MB
constexpr long OFF_XT_L = 48 * MB;
constexpr long OFF_WQT_H = 64 * MB;   // Wq^T split   [E][E]           2MB
constexpr long OFF_WQT_L = 66 * MB;
constexpr long OFF_WKT_H = 68 * MB;
constexpr long OFF_WKT_L = 70 * MB;
constexpr long OFF_WVT_H = 72 * MB;
constexpr long OFF_WVT_L = 74 * MB;
constexpr long OFF_WO_H  = 76 * MB;   // Wo split (no transpose)
constexpr long OFF_WO_L  = 78 * MB;
constexpr long OFF_P_H   = 80 * MB;   // P = Wq^T Wk
constexpr long OFF_P_L   = 82 * MB;
constexpr long OFF_Q_H   = 84 * MB;   // Q = Wo Wv
constexpr long OFF_Q_L   = 86 * MB;
constexpr long OFF_G_H   = 88 * MB;   // G  [B][E][E]  8MB
constexpr long OFF_G_L   = 96 * MB;
constexpr long OFF_R_H   = 104 * MB;  // R = Q G
constexpr long OFF_R_L   = 112 * MB;
constexpr long OFF_UT_H  = 120 * MB;  // U^T
constexpr long OFF_UT_L  = 128 * MB;
constexpr long OFF_VEC   = 136 * MB;  // fp32 vectors
constexpr long SCRATCH_BYTES = 138 * MB;

__device__ __align__(1024) char g_scratch[SCRATCH_BYTES];

// ===========================================================================
// helpers
// ===========================================================================
__device__ __forceinline__ uint32_t smem_u32(const void* p) {
    uint32_t a;
    asm("{ .reg .u64 t; cvta.to.shared.u64 t, %1; cvt.u32.u64 %0, t; }" : "=r"(a) : "l"(p));
    return a;
}
#define SWZ128(o) ((o) ^ (((o) >> 3) & 0x70))

__device__ __forceinline__ void split1(float v, float& h, float& l) {
    h = __bfloat162float(__float2bfloat16(v));
    l = v - h;
}
__device__ __forceinline__ uint32_t pack2(float a, float b) {
    __nv_bfloat16 ha = __float2bfloat16(a), hb = __float2bfloat16(b);
    uint16_t ua, ub;
    memcpy(&ua, &ha, 2); memcpy(&ub, &hb, 2);
    return (uint32_t)ua | ((uint32_t)ub << 16);
}

#define LDMX4(r0, r1, r2, r3, addr)                                            \
    asm volatile("ldmatrix.sync.aligned.m8n8.x4.shared.b16 {%0,%1,%2,%3}, [%4];" \
                 : "=r"(r0), "=r"(r1), "=r"(r2), "=r"(r3) : "r"(addr))

__device__ __forceinline__ void mma16816(float* c, const uint32_t* a, const uint32_t* b) {
    asm volatile(
        "mma.sync.aligned.m16n8k16.row.col.f32.bf16.bf16.f32 "
        "{%0,%1,%2,%3},{%4,%5,%6,%7},{%8,%9},{%0,%1,%2,%3};"
        : "+f"(c[0]), "+f"(c[1]), "+f"(c[2]), "+f"(c[3])
        : "r"(a[0]), "r"(a[1]), "r"(a[2]), "r"(a[3]), "r"(b[0]), "r"(b[1]));
}
__device__ __forceinline__ void cp16(uint32_t dst, const void* src) {
    asm volatile("cp.async.cg.shared.global [%0], [%1], 16;" :: "r"(dst), "l"(src));
}

// ===========================================================================
// preprocessing: fp32 -> bf16 hi/lo (elementwise + transposed)
// ===========================================================================
__global__ void split_k(const float* __restrict__ in,
                        __nv_bfloat16* __restrict__ oh,
                        __nv_bfloat16* __restrict__ ol, long n4) {
    long i = (long)blockIdx.x * blockDim.x + threadIdx.x;
    if (i >= n4) return;
    float4 v = ((const float4*)in)[i];
    float h0, l0, h1, l1, h2, l2, h3, l3;
    split1(v.x, h0, l0); split1(v.y, h1, l1);
    split1(v.z, h2, l2); split1(v.w, h3, l3);
    ((uint2*)oh)[i] = make_uint2(pack2(h0, h1), pack2(h2, h3));
    ((uint2*)ol)[i] = make_uint2(pack2(l0, l1), pack2(l2, l3));
}

// in: [R][C] fp32 (batch z, stride sIn elems) -> out: [C][R] bf16 hi/lo
__global__ void tsplit_k(const float* __restrict__ in, long sIn,
                         __nv_bfloat16* __restrict__ oh,
                         __nv_bfloat16* __restrict__ ol, long sOut,
                         int R, int C) {
    __shared__ float t[32][33];
    in += (long)blockIdx.z * sIn;
    oh += (long)blockIdx.z * sOut;
    ol += (long)blockIdx.z * sOut;
    int c0 = blockIdx.x * 32, r0 = blockIdx.y * 32;
    int tx = threadIdx.x, ty = threadIdx.y;  // (32,8)
#pragma unroll
    for (int i = 0; i < 4; i++)
        t[ty + i * 8][tx] = in[(long)(r0 + ty + i * 8) * C + c0 + tx];
    __syncthreads();
#pragma unroll
    for (int i = 0; i < 4; i++) {
        float v = t[tx][ty + i * 8];
        float h, l;
        split1(v, h, l);
        long o = (long)(c0 + ty + i * 8) * R + r0 + tx;
        oh[o] = __float2bfloat16(h);
        ol[o] = __float2bfloat16(l);
    }
}

// ===========================================================================
// small vector kernels (fp32)
// ===========================================================================
__global__ void coldot_k(const float* __restrict__ A, long sA,
                         const float* __restrict__ w, long sw,
                         float* __restrict__ y, int sy, int rows, int ldr) {
    A += (long)blockIdx.y * sA;
    if (w) w += (long)blockIdx.y * sw;
    y += blockIdx.y * sy;
    int j = blockIdx.x * blockDim.x + threadIdx.x;
    float acc = 0.f;
#pragma unroll 8
    for (int i = 0; i < rows; i++) {
        float wv = w ? w[i] : 1.f;
        acc += A[(long)i * ldr + j] * wv;
    }
    y[j] = acc;
}

__global__ void rowdot_k(const float* __restrict__ A,
                         const float* __restrict__ xv, int sxv,
                         const float* __restrict__ bias,
                         float* __restrict__ y, int sy, int cols, float alpha) {
    xv += blockIdx.y * sxv;
    y  += blockIdx.y * sy;
    int warp = blockIdx.x * (blockDim.x >> 5) + (threadIdx.x >> 5);
    int lane = threadIdx.x & 31;
    const float* row = A + (long)warp * cols;
    float acc = 0.f;
    for (int j = lane; j < cols; j += 32) acc += row[j] * xv[j];
#pragma unroll
    for (int o = 16; o > 0; o >>= 1) acc += __shfl_xor_sync(0xffffffffu, acc, o);
    if (lane == 0) y[warp] = alpha * acc + (bias ? bias[warp] : 0.f);
}

// y_b[i] = dot((Ah+Al)[i,:], xv)  over split bf16 matrix (batched)
__global__ void rowdot_bf2_k(const __nv_bfloat16* __restrict__ Ah,
                             const __nv_bfloat16* __restrict__ Al, long sA,
                             const float* __restrict__ xv,
                             float* __restrict__ y, int sy, int cols) {
    Ah += (long)blockIdx.y * sA;
    Al += (long)blockIdx.y * sA;
    y  += blockIdx.y * sy;
    int warp = blockIdx.x * (blockDim.x >> 5) + (threadIdx.x >> 5);
    int lane = threadIdx.x & 31;
    const __nv_bfloat16* rh = Ah + (long)warp * cols;
    const __nv_bfloat16* rl = Al + (long)warp * cols;
    float acc = 0.f;
    for (int j = lane; j < cols; j += 32)
        acc += (__bfloat162float(rh[j]) + __bfloat162float(rl[j])) * xv[j];
#pragma unroll
    for (int o = 16; o > 0; o >>= 1) acc += __shfl_xor_sync(0xffffffffu, acc, o);
    if (lane == 0) y[warp] = acc;
}

__global__ void dot_k(const float* __restrict__ a, long sa,
                      const float* __restrict__ b, float* __restrict__ y, int n) {
    a += (long)blockIdx.x * sa;
    __shared__ float red[8];
    int tid = threadIdx.x;
    float acc = 0.f;
    for (int j = tid; j < n; j += 256) acc += a[j] * b[j];
#pragma unroll
    for (int o = 16; o > 0; o >>= 1) acc += __shfl_xor_sync(0xffffffffu, acc, o);
    if ((tid & 31) == 0) red[tid >> 5] = acc;
    __syncthreads();
    if (tid < 8) {
        float v = red[tid];
#pragma unroll
        for (int o = 4; o > 0; o >>= 1) v += __shfl_xor_sync(0xffu, v, o);
        if (tid == 0) y[blockIdx.x] = v;
    }
}

// d_b[i] = wvt2_b[i] + bv[i]*(dp[b] + S*db) + r_b[i]*db
__global__ void vfin_k(float* __restrict__ d, const float* __restrict__ wvt2,
                       const float* __restrict__ bv, const float* __restrict__ r,
                       const float* __restrict__ dp, const float* __restrict__ db) {
    int b = blockIdx.y;
    int i = blockIdx.x * 256 + threadIdx.x;
    float dbv = db[0];
    d[(long)b * Ed + i] = wvt2[(long)b * Ed + i]
                        + bv[i] * (dp[b] + (float)Sd * dbv)
                        + r[(long)b * Ed + i] * dbv;
}

// ===========================================================================
// bf16 hi/lo split GEMM engine (cp.async double-buffered, mma.sync core)
//   C = alpha * A B^T  where A[m][k], B[n][k], both bf16 hi/lo K-major
//   mode 1: C += v1[m]*v2[n] + v3[m]*(v4[n] + rk*v2[n])
//   mode 2: C += v1[n]
// outputs: optional fp32 Cf, optional bf16 split Ch/Cl
// Block tile 128x128, K-chunk 64, 8 warps (warp tile 32x64)
// ===========================================================================
constexpr int STAGE  = 65536;
constexpr int OFF_AH = 0;
constexpr int OFF_AL = 16384;
constexpr int OFF_BH = 32768;
constexpr int OFF_BL = 49152;
constexpr int DYN_SMEM = 2 * STAGE;  // 128 KB

__device__ __forceinline__ void issue_tile(uint32_t sdst, const __nv_bfloat16* g,
                                           long ldK, int tid) {
#pragma unroll
    for (int i = 0; i < 4; i++) {
        int gi = tid + i * 256;
        int row = gi >> 3, c16 = gi & 7;
        uint32_t off = SWZ128((uint32_t)(row * 128 + c16 * 16));
        cp16(sdst + off, (const char*)(g + (long)row * ldK) + c16 * 16);
    }
}

__device__ __forceinline__ void compute_ks(uint32_t sb, int ks, int m_warp, int n_warp,
                                           int lane, float (&acc)[2][8][4]) {
    const uint32_t rowsel = lane & 15;
    const uint32_t ksel = (lane >> 4) * 16;
    uint32_t ah[2][4], al[2][4];
#pragma unroll
    for (int mt = 0; mt < 2; mt++) {
        uint32_t off = SWZ128((uint32_t)((m_warp + mt * 16 + rowsel) * 128 + ks * 32 + ksel));
        LDMX4(ah[mt][0], ah[mt][1], ah[mt][2], ah[mt][3], sb + OFF_AH + off);
        LDMX4(al[mt][0], al[mt][1], al[mt][2], al[mt][3], sb + OFF_AL + off);
    }
    uint32_t bh[8][2], bl[8][2];
#pragma unroll
    for (int nt = 0; nt < 4; nt++) {
        uint32_t off = SWZ128((uint32_t)((n_warp + nt * 16 + rowsel) * 128 + ks * 32 + ksel));
        uint32_t r0, r1, r2, r3;
        LDMX4(r0, r1, r2, r3, sb + OFF_BH + off);
        bh[2 * nt][0] = r0; bh[2 * nt][1] = r2;
        bh[2 * nt + 1][0] = r1; bh[2 * nt + 1][1] = r3;
        LDMX4(r0, r1, r2, r3, sb + OFF_BL + off);
        bl[2 * nt][0] = r0; bl[2 * nt][1] = r2;
        bl[2 * nt + 1][0] = r1; bl[2 * nt + 1][1] = r3;
    }
#pragma unroll
    for (int mt = 0; mt < 2; mt++)
#pragma unroll
        for (int nf = 0; nf < 8; nf++) {
            mma16816(acc[mt][nf], ah[mt], bh[nf]);  // hi*hi
            mma16816(acc[mt][nf], ah[mt], bl[nf]);  // hi*lo
            mma16816(acc[mt][nf], al[mt], bh[nf]);  // lo*hi
        }
}

__global__ void __launch_bounds__(256, 1) bf_gemm(
    const __nv_bfloat16* __restrict__ Ah, const __nv_bfloat16* __restrict__ Al, long sA,
    const __nv_bfloat16* __restrict__ Bh, const __nv_bfloat16* __restrict__ Bl, long sB,
    float* __restrict__ Cf, long sCf,
    __nv_bfloat16* __restrict__ Ch, __nv_bfloat16* __restrict__ Cl, long sCb,
    int Nd, int Kd, float alpha, int mode,
    const float* __restrict__ v1, int sv1, const float* __restrict__ v2,
    const float* __restrict__ v3, const float* __restrict__ v4, int sv4, float rk)
{
    extern __shared__ char smem[];
    const int bz = blockIdx.z;
    Ah += (long)bz * sA; Al += (long)bz * sA;
    Bh += (long)bz * sB; Bl += (long)bz * sB;
    if (Cf) Cf += (long)bz * sCf;
    if (Ch) { Ch += (long)bz * sCb; Cl += (long)bz * sCb; }
    if (v1) v1 += (long)bz * sv1;
    if (v4) v4 += (long)bz * sv4;

    const int m0 = blockIdx.y * 128;
    const int n0 = blockIdx.x * 128;
    const int tid = threadIdx.x;
    const int wid = tid >> 5;
    const int lane = tid & 31;
    const int m_warp = (wid >> 1) * 32;
    const int n_warp = (wid & 1) * 64;
    const uint32_t sbase = smem_u32(smem);

    float acc[2][8][4];
#pragma unroll
    for (int mt = 0; mt < 2; mt++)
#pragma unroll
        for (int nf = 0; nf < 8; nf++)
#pragma unroll
            for (int q = 0; q < 4; q++) acc[mt][nf][q] = 0.f;

    const int nCh = Kd / 64;
    auto issue = [&](int c) {
        uint32_t sb = sbase + (c & 1) * STAGE;
        long k0 = (long)c * 64;
        issue_tile(sb + OFF_AH, Ah + (long)m0 * Kd + k0, Kd, tid);
        issue_tile(sb + OFF_AL, Al + (long)m0 * Kd + k0, Kd, tid);
        issue_tile(sb + OFF_BH, Bh + (long)n0 * Kd + k0, Kd, tid);
        issue_tile(sb + OFF_BL, Bl + (long)n0 * Kd + k0, Kd, tid);
        asm volatile("cp.async.commit_group;" ::: "memory");
    };

    issue(0);
    for (int c = 0; c < nCh; c++) {
        if (c + 1 < nCh) {
            issue(c + 1);
            asm volatile("cp.async.wait_group 1;" ::: "memory");
        } else {
            asm volatile("cp.async.wait_group 0;" ::: "memory");
        }
        __syncthreads();
        const uint32_t sb = sbase + (c & 1) * STAGE;
        compute_ks(sb, 0, m_warp, n_warp, lane, acc);
        compute_ks(sb, 1, m_warp, n_warp, lane, acc);
        compute_ks(sb, 2, m_warp, n_warp, lane, acc);
        compute_ks(sb, 3, m_warp, n_warp, lane, acc);
        __syncthreads();
    }

    // epilogue
    const int r = lane >> 2;
    const int cp = (lane & 3) * 2;
#pragma unroll
    for (int mt = 0; mt < 2; mt++)
#pragma unroll
        for (int rr = 0; rr < 2; rr++) {
            const int m = m0 + m_warp + mt * 16 + r + rr * 8;
            float pv = 0.f, bkv = 0.f;
            if (mode == 1) { pv = v1[m]; bkv = v3[m]; }
#pragma unroll
            for (int nf = 0; nf < 8; nf++) {
                const int nloc = nf * 8 + cp;
                const int n = n0 + n_warp + nloc;
                float f0 = alpha * acc[mt][nf][rr * 2 + 0];
                float f1 = alpha * acc[mt][nf][rr * 2 + 1];
                if (mode == 1) {
                    f0 += pv * v2[n + 0] + bkv * (v4[n + 0] + rk * v2[n + 0]);
                    f1 += pv * v2[n + 1] + bkv * (v4[n + 1] + rk * v2[n + 1]);
                } else if (mode == 2) {
                    f0 += v1[n + 0];
                    f1 += v1[n + 1];
                }
                long co = (long)m * Nd + n0 + n_warp + nloc;
                if (Cf) *(float2*)(Cf + co) = make_float2(f0, f1);
                if (Ch) {
                    float h0, l0, h1, l1;
                    split1(f0, h0, l0);
                    split1(f1, h1, l1);
                    *(uint32_t*)(Ch + co) = pack2(h0, h1);
                    *(uint32_t*)(Cl + co) = pack2(l0, l1);
                }
            }
        }
}

// ===========================================================================
// Launch.
//   P = Wq^T Wk, Q = Wo Wv (batch-independent)
//   G_b = x^T x ; R_b = Q G_b ; UT_b = R_b P^T + w2 u2^T + w1(u1 + S u2)^T
//   out_b = SCALE * x UT^T + c_b
//   c_b = SCALE * Wo (Wv (G t1) + bv(p.bq) + r(bk.bq) + S bv(bk.bq)) + bo
// ===========================================================================
extern "C" void kernel_launch(void* const* d_in, const int* in_sizes, int n_in,
                              void* d_out, int out_size)
{
    const float* x  = (const float*)d_in[0];
    const float* Wq = (const float*)d_in[1];
    const float* bq = (const float*)d_in[2];
    const float* Wk = (const float*)d_in[3];
    const float* bk = (const float*)d_in[4];
    const float* Wv = (const float*)d_in[5];
    const float* bv = (const float*)d_in[6];
    const float* Wo = (const float*)d_in[7];
    const float* bo = (const float*)d_in[8];
    float* out = (float*)d_out;

    char* scr = nullptr;
    cudaGetSymbolAddress((void**)&scr, g_scratch);
    auto BF = [&](long off) { return (__nv_bfloat16*)(scr + off); };

    __nv_bfloat16 *xs_h = BF(OFF_XS_H), *xs_l = BF(OFF_XS_L);
    __nv_bfloat16 *xt_h = BF(OFF_XT_H), *xt_l = BF(OFF_XT_L);
    __nv_bfloat16 *wqt_h = BF(OFF_WQT_H), *wqt_l = BF(OFF_WQT_L);
    __nv_bfloat16 *wkt_h = BF(OFF_WKT_H), *wkt_l = BF(OFF_WKT_L);
    __nv_bfloat16 *wvt_h = BF(OFF_WVT_H), *wvt_l = BF(OFF_WVT_L);
    __nv_bfloat16 *wo_h  = BF(OFF_WO_H),  *wo_l  = BF(OFF_WO_L);
    __nv_bfloat16 *P_h = BF(OFF_P_H), *P_l = BF(OFF_P_L);
    __nv_bfloat16 *Q_h = BF(OFF_Q_H), *Q_l = BF(OFF_Q_L);
    __nv_bfloat16 *G_h = BF(OFF_G_H), *G_l = BF(OFF_G_L);
    __nv_bfloat16 *R_h = BF(OFF_R_H), *R_l = BF(OFF_R_L);
    __nv_bfloat16 *UT_h = BF(OFF_UT_H), *UT_l = BF(OFF_UT_L);

    float* vec = (float*)(scr + OFF_VEC);
    float* s    = vec;                 // [B][E]
    float* p    = s    + Bd * Ed;      // [B][E]
    float* r    = p    + Bd * Ed;
    float* u1   = r    + Bd * Ed;
    float* w2   = u1   + Bd * Ed;
    float* t2   = w2   + Bd * Ed;
    float* wvt2 = t2   + Bd * Ed;
    float* d    = wvt2 + Bd * Ed;
    float* cb   = d    + Bd * Ed;      // c_b [B][E]
    float* u2   = cb   + Bd * Ed;      // [E]
    float* w1   = u2   + Ed;
    float* t1   = w1   + Ed;
    float* dp   = t1   + Ed;           // [B]
    float* db   = dp   + Bd;           // [1]

    const long sX = (long)Sd * Ed;     // 2M elems, x / xs / out stride
    const long sXT = (long)Ed * Sd;    // xT stride
    const long sEE = (long)Ed * Ed;    // 1M elems

    cudaFuncSetAttribute(bf_gemm, cudaFuncAttributeMaxDynamicSharedMemorySize, DYN_SMEM);

    // ---- preprocessing: splits + transposed splits ----
    split_k<<<(Bd * sX / 4 + 255) / 256, 256>>>(x, xs_h, xs_l, Bd * sX / 4);
    split_k<<<(sEE / 4 + 255) / 256, 256>>>(Wo, wo_h, wo_l, sEE / 4);
    tsplit_k<<<dim3(Ed / 32, Sd / 32, Bd), dim3(32, 8)>>>(x, sX, xt_h, xt_l, sXT, Sd, Ed);
    tsplit_k<<<dim3(Ed / 32, Ed / 32, 1), dim3(32, 8)>>>(Wq, 0, wqt_h, wqt_l, 0, Ed, Ed);
    tsplit_k<<<dim3(Ed / 32, Ed / 32, 1), dim3(32, 8)>>>(Wk, 0, wkt_h, wkt_l, 0, Ed, Ed);
    tsplit_k<<<dim3(Ed / 32, Ed / 32, 1), dim3(32, 8)>>>(Wv, 0, wvt_h, wvt_l, 0, Ed, Ed);

    // ---- vectors (fp32 exact) ----
    coldot_k<<<dim3(Ed / 256, Bd), 256>>>(x, sX, nullptr, 0, s, Ed, Sd, Ed);     // s = colsum x
    rowdot_k<<<dim3(Ed / 8, Bd), 256>>>(Wk, s, Ed, nullptr, p, Ed, Ed, 1.f);     // p = Wk s
    rowdot_k<<<dim3(Ed / 8, Bd), 256>>>(Wv, s, Ed, nullptr, r, Ed, Ed, 1.f);     // r = Wv s
    coldot_k<<<dim3(Ed / 256, Bd), 256>>>(Wq, 0, p, Ed, u1, Ed, Ed, Ed);         // u1 = Wq^T p
    coldot_k<<<dim3(Ed / 256, 1), 256>>>(Wq, 0, bk, 0, u2, 0, Ed, Ed);           // u2 = Wq^T bk
    coldot_k<<<dim3(Ed / 256, 1), 256>>>(Wk, 0, bq, 0, t1, 0, Ed, Ed);           // t1 = Wk^T bq
    rowdot_k<<<dim3(Ed / 8, 1), 256>>>(Wo, bv, 0, nullptr, w1, 0, Ed, 1.f);      // w1 = Wo bv
    rowdot_k<<<dim3(Ed / 8, Bd), 256>>>(Wo, r, Ed, nullptr, w2, Ed, Ed, 1.f);    // w2 = Wo r
    dot_k<<<Bd, 256>>>(p, Ed, bq, dp, Ed);                                       // dp = p.bq
    dot_k<<<1, 256>>>(bk, 0, bq, db, Ed);                                        // db = bk.bq

    // ---- GEMMs ----
    dim3 blk(256);
    // P = Wq^T Wk  : A=WqT, B=WkT
    bf_gemm<<<dim3(8, 8, 1), blk, DYN_SMEM>>>(wqt_h, wqt_l, 0, wkt_h, wkt_l, 0,
        nullptr, 0, P_h, P_l, 0, Ed, Ed, 1.f, 0,
        nullptr, 0, nullptr, nullptr, nullptr, 0, 0.f);
    // Q = Wo Wv   : A=Wo, B=WvT
    bf_gemm<<<dim3(8, 8, 1), blk, DYN_SMEM>>>(wo_h, wo_l, 0, wvt_h, wvt_l, 0,
        nullptr, 0, Q_h, Q_l, 0, Ed, Ed, 1.f, 0,
        nullptr, 0, nullptr, nullptr, nullptr, 0, 0.f);
    // G_b = x^T x : A=B=xT, K=S
    bf_gemm<<<dim3(8, 8, Bd), blk, DYN_SMEM>>>(xt_h, xt_l, sXT, xt_h, xt_l, sXT,
        nullptr, 0, G_h, G_l, sEE, Ed, Sd, 1.f, 0,
        nullptr, 0, nullptr, nullptr, nullptr, 0, 0.f);

    // t2 = G t1 ; wvt2 = Wv t2 ; d ; c = SCALE*Wo d + bo
    rowdot_bf2_k<<<dim3(Ed / 8, Bd), 256>>>(G_h, G_l, sEE, t1, t2, Ed, Ed);
    rowdot_k<<<dim3(Ed / 8, Bd), 256>>>(Wv, t2, Ed, nullptr, wvt2, Ed, Ed, 1.f);
    vfin_k<<<dim3(Ed / 256, Bd), 256>>>(d, wvt2, bv, r, dp, db);
    rowdot_k<<<dim3(Ed / 8, Bd), 256>>>(Wo, d, Ed, bo, cb, Ed, Ed, SCALE_F);

    // R_b = Q G_b : A=Q (shared), B=G_b (symmetric -> row-major ok)
    bf_gemm<<<dim3(8, 8, Bd), blk, DYN_SMEM>>>(Q_h, Q_l, 0, G_h, G_l, sEE,
        nullptr, 0, R_h, R_l, sEE, Ed, Ed, 1.f, 0,
        nullptr, 0, nullptr, nullptr, nullptr, 0, 0.f);
    // UT_b = R_b P^T + w2 u2^T + w1 (u1 + S u2)^T
    bf_gemm<<<dim3(8, 8, Bd), blk, DYN_SMEM>>>(R_h, R_l, sEE, P_h, P_l, 0,
        nullptr, 0, UT_h, UT_l, sEE, Ed, Ed, 1.f, 1,
        w2, Ed, u2, w1, u1, Ed, (float)Sd);
    // out_b = SCALE * x UT^T + c_b
    bf_gemm<<<dim3(8, 16, Bd), blk, DYN_SMEM>>>(xs_h, xs_l, sX, UT_h, UT_l, sEE,
        out, sX, nullptr, nullptr, 0, Ed, Ed, SCALE_F, 2,
        cb, Ed, nullptr, nullptr, nullptr, 0, 0.f);
}

// round 6
// speedup vs baseline: 3.4658x; 1.1570x over previous
#include <cuda_runtime.h>
#include <cuda_bf16.h>
#include <cstdint>
#include <cstring>

// Problem dims (fixed by setup_inputs)
constexpr int Bd = 4;
constexpr int Sd = 2048;
constexpr int Ed = 1024;
constexpr float SCALE_F = 0.125f;

// ===========================================================================
// scratch layout (bytes)
// ===========================================================================
constexpr long MB = 1024 * 1024;
constexpr long OFF_XS_H = 0;          // x split      [B][S][E] bf16  16MB
constexpr long OFF_XS_L = 16 * MB;
constexpr long OFF_XT_H = 32 * MB;    // x^T split    [B][E][S] bf16  16MB
constexpr long OFF_XT_L = 48 * MB;
constexpr long OFF_WQT_H = 64 * MB;   // Wq^T split   [E][E]           2MB
constexpr long OFF_WQT_L = 66 * MB;
constexpr long OFF_WKT_H = 68 * MB;
constexpr long OFF_WKT_L = 70 * MB;
constexpr long OFF_WVT_H = 72 * MB;
constexpr long OFF_WVT_L = 74 * MB;
constexpr long OFF_WO_H  = 76 * MB;   // Wo split (no transpose)
constexpr long OFF_WO_L  = 78 * MB;
constexpr long OFF_P_H   = 80 * MB;   // P = Wq^T Wk
constexpr long OFF_P_L   = 82 * MB;
constexpr long OFF_Q_H   = 84 * MB;   // Q = Wo Wv
constexpr long OFF_Q_L   = 86 * MB;
constexpr long OFF_G_H   = 88 * MB;   // G  [B][E][E]  8MB
constexpr long OFF_G_L   = 96 * MB;
constexpr long OFF_R_H   = 104 * MB;  // R = Q G
constexpr long OFF_R_L   = 112 * MB;
constexpr long OFF_UT_H  = 120 * MB;  // U^T
constexpr long OFF_UT_L  = 128 * MB;
constexpr long OFF_VEC   = 136 * MB;  // fp32 vectors
constexpr long SCRATCH_BYTES = 138 * MB;

__device__ __align__(1024) char g_scratch[SCRATCH_BYTES];

// ===========================================================================
// helpers
// ===========================================================================
__device__ __forceinline__ uint32_t smem_u32(const void* p) {
    uint32_t a;
    asm("{ .reg .u64 t; cvta.to.shared.u64 t, %1; cvt.u32.u64 %0, t; }" : "=r"(a) : "l"(p));
    return a;
}
#define SWZ128(o) ((o) ^ (((o) >> 3) & 0x70))

__device__ __forceinline__ void split1(float v, float& h, float& l) {
    h = __bfloat162float(__float2bfloat16(v));
    l = v - h;
}
__device__ __forceinline__ uint32_t pack2(float a, float b) {
    __nv_bfloat16 ha = __float2bfloat16(a), hb = __float2bfloat16(b);
    uint16_t ua, ub;
    memcpy(&ua, &ha, 2); memcpy(&ub, &hb, 2);
    return (uint32_t)ua | ((uint32_t)ub << 16);
}

#define LDMX4(r0, r1, r2, r3, addr)                                            \
    asm volatile("ldmatrix.sync.aligned.m8n8.x4.shared.b16 {%0,%1,%2,%3}, [%4];" \
                 : "=r"(r0), "=r"(r1), "=r"(r2), "=r"(r3) : "r"(addr))

__device__ __forceinline__ void mma16816(float* c, const uint32_t* a, const uint32_t* b) {
    asm volatile(
        "mma.sync.aligned.m16n8k16.row.col.f32.bf16.bf16.f32 "
        "{%0,%1,%2,%3},{%4,%5,%6,%7},{%8,%9},{%0,%1,%2,%3};"
        : "+f"(c[0]), "+f"(c[1]), "+f"(c[2]), "+f"(c[3])
        : "r"(a[0]), "r"(a[1]), "r"(a[2]), "r"(a[3]), "r"(b[0]), "r"(b[1]));
}
__device__ __forceinline__ void cp16(uint32_t dst, const void* src) {
    asm volatile("cp.async.cg.shared.global [%0], [%1], 16;" :: "r"(dst), "l"(src));
}

// ===========================================================================
// preprocessing: fp32 -> bf16 hi/lo (elementwise + transposed)
// ===========================================================================
__global__ void split_k(const float* __restrict__ in,
                        __nv_bfloat16* __restrict__ oh,
                        __nv_bfloat16* __restrict__ ol, long n4) {
    long i = (long)blockIdx.x * blockDim.x + threadIdx.x;
    if (i >= n4) return;
    float4 v = ((const float4*)in)[i];
    float h0, l0, h1, l1, h2, l2, h3, l3;
    split1(v.x, h0, l0); split1(v.y, h1, l1);
    split1(v.z, h2, l2); split1(v.w, h3, l3);
    ((uint2*)oh)[i] = make_uint2(pack2(h0, h1), pack2(h2, h3));
    ((uint2*)ol)[i] = make_uint2(pack2(l0, l1), pack2(l2, l3));
}

// in: [R][C] fp32 (batch z, stride sIn elems) -> out: [C][R] bf16 hi/lo
__global__ void tsplit_k(const float* __restrict__ in, long sIn,
                         __nv_bfloat16* __restrict__ oh,
                         __nv_bfloat16* __restrict__ ol, long sOut,
                         int R, int C) {
    __shared__ float t[32][33];
    in += (long)blockIdx.z * sIn;
    oh += (long)blockIdx.z * sOut;
    ol += (long)blockIdx.z * sOut;
    int c0 = blockIdx.x * 32, r0 = blockIdx.y * 32;
    int tx = threadIdx.x, ty = threadIdx.y;  // (32,8)
#pragma unroll
    for (int i = 0; i < 4; i++)
        t[ty + i * 8][tx] = in[(long)(r0 + ty + i * 8) * C + c0 + tx];
    __syncthreads();
#pragma unroll
    for (int i = 0; i < 4; i++) {
        float v = t[tx][ty + i * 8];
        float h, l;
        split1(v, h, l);
        long o = (long)(c0 + ty + i * 8) * R + r0 + tx;
        oh[o] = __float2bfloat16(h);
        ol[o] = __float2bfloat16(l);
    }
}

// mirror upper-triangle tiles of symmetric bf16 matrix into lower triangle
// grid: (Ed/32, Ed/32, Bd*2)  block (32,8). z selects batch + h/l array.
__global__ void mirror_k(__nv_bfloat16* __restrict__ Gh,
                         __nv_bfloat16* __restrict__ Gl, long sEE) {
    int bi = blockIdx.y, bj = blockIdx.x;   // source tile (rows bi, cols bj), bi<=bj
    if (bi > bj) return;
    __nv_bfloat16* G = ((blockIdx.z & 1) ? Gl : Gh) + (long)(blockIdx.z >> 1) * sEE;
    __shared__ uint16_t t[32][33];
    int tx = threadIdx.x, ty = threadIdx.y;
    int r0 = bi * 32, c0 = bj * 32;
#pragma unroll
    for (int i = 0; i < 4; i++) {
        int r = ty + i * 8;
        uint16_t v;
        memcpy(&v, &G[(long)(r0 + r) * Ed + c0 + tx], 2);
        t[r][tx] = v;
    }
    __syncthreads();
#pragma unroll
    for (int i = 0; i < 4; i++) {
        int rr = ty + i * 8;             // dest row within tile (bj)
        int cc = tx;                     // dest col within tile (bi)
        int dr = c0 + rr, dc = r0 + cc;  // dest global (transposed)
        if (dr > dc) {
            uint16_t v = t[cc][rr];
            memcpy(&G[(long)dr * Ed + dc], &v, 2);
        }
    }
}

// ===========================================================================
// small vector kernels (fp32)
// ===========================================================================
__global__ void coldot_k(const float* __restrict__ A, long sA,
                         const float* __restrict__ w, long sw,
                         float* __restrict__ y, int sy, int rows, int ldr) {
    A += (long)blockIdx.y * sA;
    if (w) w += (long)blockIdx.y * sw;
    y += blockIdx.y * sy;
    int j = blockIdx.x * blockDim.x + threadIdx.x;
    float acc = 0.f;
#pragma unroll 8
    for (int i = 0; i < rows; i++) {
        float wv = w ? w[i] : 1.f;
        acc += A[(long)i * ldr + j] * wv;
    }
    y[j] = acc;
}

// z=0: y=u2=Wq^T bk ; z=1: y=t1=Wk^T bq
__global__ void coldot2_k(const float* __restrict__ Wq, const float* __restrict__ bk,
                          const float* __restrict__ Wk, const float* __restrict__ bq,
                          float* __restrict__ u2, float* __restrict__ t1) {
    const float* A = blockIdx.z ? Wk : Wq;
    const float* w = blockIdx.z ? bq : bk;
    float* y = blockIdx.z ? t1 : u2;
    int j = blockIdx.x * blockDim.x + threadIdx.x;
    float acc = 0.f;
#pragma unroll 8
    for (int i = 0; i < Ed; i++) acc += A[(long)i * Ed + j] * w[i];
    y[j] = acc;
}

__global__ void rowdot_k(const float* __restrict__ A,
                         const float* __restrict__ xv, int sxv,
                         const float* __restrict__ bias,
                         float* __restrict__ y, int sy, int cols, float alpha) {
    xv += blockIdx.y * sxv;
    y  += blockIdx.y * sy;
    int warp = blockIdx.x * (blockDim.x >> 5) + (threadIdx.x >> 5);
    int lane = threadIdx.x & 31;
    const float* row = A + (long)warp * cols;
    float acc = 0.f;
    for (int j = lane; j < cols; j += 32) acc += row[j] * xv[j];
#pragma unroll
    for (int o = 16; o > 0; o >>= 1) acc += __shfl_xor_sync(0xffffffffu, acc, o);
    if (lane == 0) y[warp] = alpha * acc + (bias ? bias[warp] : 0.f);
}

// z=0: p_b = Wk s_b ; z=1: r_b = Wv s_b
__global__ void rowdot_pr_k(const float* __restrict__ Wk, const float* __restrict__ Wv,
                            const float* __restrict__ s,
                            float* __restrict__ p, float* __restrict__ r) {
    const float* A = blockIdx.z ? Wv : Wk;
    float* y = (blockIdx.z ? r : p) + blockIdx.y * Ed;
    const float* xv = s + blockIdx.y * Ed;
    int warp = blockIdx.x * 8 + (threadIdx.x >> 5);
    int lane = threadIdx.x & 31;
    const float* row = A + (long)warp * Ed;
    float acc = 0.f;
    for (int j = lane; j < Ed; j += 32) acc += row[j] * xv[j];
#pragma unroll
    for (int o = 16; o > 0; o >>= 1) acc += __shfl_xor_sync(0xffffffffu, acc, o);
    if (lane == 0) y[warp] = acc;
}

// y_b[i] = dot((Ah+Al)[i,:], xv)  over split bf16 matrix (batched)
__global__ void rowdot_bf2_k(const __nv_bfloat16* __restrict__ Ah,
                             const __nv_bfloat16* __restrict__ Al, long sA,
                             const float* __restrict__ xv,
                             float* __restrict__ y, int sy, int cols) {
    Ah += (long)blockIdx.y * sA;
    Al += (long)blockIdx.y * sA;
    y  += blockIdx.y * sy;
    int warp = blockIdx.x * (blockDim.x >> 5) + (threadIdx.x >> 5);
    int lane = threadIdx.x & 31;
    const __nv_bfloat16* rh = Ah + (long)warp * cols;
    const __nv_bfloat16* rl = Al + (long)warp * cols;
    float acc = 0.f;
    for (int j = lane; j < cols; j += 32)
        acc += (__bfloat162float(rh[j]) + __bfloat162float(rl[j])) * xv[j];
#pragma unroll
    for (int o = 16; o > 0; o >>= 1) acc += __shfl_xor_sync(0xffffffffu, acc, o);
    if (lane == 0) y[warp] = acc;
}

// blocks 0..Bd-1: dp[b] = p_b . bq ; block Bd: db = bk . bq
__global__ void dot2_k(const float* __restrict__ p, const float* __restrict__ bk,
                       const float* __restrict__ bq,
                       float* __restrict__ dp, float* __restrict__ db) {
    int bid = blockIdx.x;
    const float* a = (bid < Bd) ? p + (long)bid * Ed : bk;
    __shared__ float red[8];
    int tid = threadIdx.x;
    float acc = 0.f;
    for (int j = tid; j < Ed; j += 256) acc += a[j] * bq[j];
#pragma unroll
    for (int o = 16; o > 0; o >>= 1) acc += __shfl_xor_sync(0xffffffffu, acc, o);
    if ((tid & 31) == 0) red[tid >> 5] = acc;
    __syncthreads();
    if (tid < 8) {
        float v = red[tid];
#pragma unroll
        for (int o = 4; o > 0; o >>= 1) v += __shfl_xor_sync(0xffu, v, o);
        if (tid == 0) { if (bid < Bd) dp[bid] = v; else db[0] = v; }
    }
}

// d_b[i] = wvt2_b[i] + bv[i]*(dp[b] + S*db) + r_b[i]*db
__global__ void vfin_k(float* __restrict__ d, const float* __restrict__ wvt2,
                       const float* __restrict__ bv, const float* __restrict__ r,
                       const float* __restrict__ dp, const float* __restrict__ db) {
    int b = blockIdx.y;
    int i = blockIdx.x * 256 + threadIdx.x;
    float dbv = db[0];
    d[(long)b * Ed + i] = wvt2[(long)b * Ed + i]
                        + bv[i] * (dp[b] + (float)Sd * dbv)
                        + r[(long)b * Ed + i] * dbv;
}

// ===========================================================================
// bf16 hi/lo split GEMM engine v2
//   512 threads (16 warps, 4x4), warp tile 32x32, block tile 128x128,
//   K-chunk 64, 3-stage cp.async pipeline.
//   C = alpha * A B^T  where A[m][k], B[n][k], both bf16 hi/lo K-major
//   mode 1: C += v1[m]*v2[n] + v3[m]*(v4[n] + rk*v2[n])
//   mode 2: C += v1[n]
//   tri != 0: grid.x in [0,36) decodes to upper-triangle tile (ti<=tj)
// ===========================================================================
constexpr int STAGE  = 65536;
constexpr int OFF_AH = 0;
constexpr int OFF_AL = 16384;
constexpr int OFF_BH = 32768;
constexpr int OFF_BL = 49152;
constexpr int DYN_SMEM = 3 * STAGE;  // 192 KB

__device__ __forceinline__ void issue_tile(uint32_t sdst, const __nv_bfloat16* g,
                                           long ldK, int tid) {
#pragma unroll
    for (int i = 0; i < 2; i++) {
        int gi = tid + i * 512;
        int row = gi >> 3, c16 = gi & 7;
        uint32_t off = SWZ128((uint32_t)(row * 128 + c16 * 16));
        cp16(sdst + off, (const char*)(g + (long)row * ldK) + c16 * 16);
    }
}

__device__ __forceinline__ void compute_ks(uint32_t sb, int ks, int mw, int nw,
                                           int lane, float (&acc)[2][4][4]) {
    const uint32_t rowsel = lane & 15;
    const uint32_t ksel = (lane >> 4) * 16;
    uint32_t ah[2][4], al[2][4];
#pragma unroll
    for (int mt = 0; mt < 2; mt++) {
        uint32_t off = SWZ128((uint32_t)((mw + mt * 16 + rowsel) * 128 + ks * 32 + ksel));
        LDMX4(ah[mt][0], ah[mt][1], ah[mt][2], ah[mt][3], sb + OFF_AH + off);
        LDMX4(al[mt][0], al[mt][1], al[mt][2], al[mt][3], sb + OFF_AL + off);
    }
    uint32_t bh[4][2], bl[4][2];
#pragma unroll
    for (int nt = 0; nt < 2; nt++) {
        uint32_t off = SWZ128((uint32_t)((nw + nt * 16 + rowsel) * 128 + ks * 32 + ksel));
        uint32_t r0, r1, r2, r3;
        LDMX4(r0, r1, r2, r3, sb + OFF_BH + off);
        bh[2 * nt][0] = r0; bh[2 * nt][1] = r2;
        bh[2 * nt + 1][0] = r1; bh[2 * nt + 1][1] = r3;
        LDMX4(r0, r1, r2, r3, sb + OFF_BL + off);
        bl[2 * nt][0] = r0; bl[2 * nt][1] = r2;
        bl[2 * nt + 1][0] = r1; bl[2 * nt + 1][1] = r3;
    }
#pragma unroll
    for (int mt = 0; mt < 2; mt++)
#pragma unroll
        for (int nf = 0; nf < 4; nf++) {
            mma16816(acc[mt][nf], ah[mt], bh[nf]);  // hi*hi
            mma16816(acc[mt][nf], ah[mt], bl[nf]);  // hi*lo
            mma16816(acc[mt][nf], al[mt], bh[nf]);  // lo*hi
        }
}

__global__ void __launch_bounds__(512, 1) bf_gemm(
    const __nv_bfloat16* __restrict__ Ah, const __nv_bfloat16* __restrict__ Al, long sA,
    const __nv_bfloat16* __restrict__ Bh, const __nv_bfloat16* __restrict__ Bl, long sB,
    float* __restrict__ Cf, long sCf,
    __nv_bfloat16* __restrict__ Ch, __nv_bfloat16* __restrict__ Cl, long sCb,
    int Nd, int Kd, float alpha, int mode, int tri,
    const float* __restrict__ v1, int sv1, const float* __restrict__ v2,
    const float* __restrict__ v3, const float* __restrict__ v4, int sv4, float rk)
{
    extern __shared__ char smem[];
    const int bz = blockIdx.z;
    Ah += (long)bz * sA; Al += (long)bz * sA;
    Bh += (long)bz * sB; Bl += (long)bz * sB;
    if (Cf) Cf += (long)bz * sCf;
    if (Ch) { Ch += (long)bz * sCb; Cl += (long)bz * sCb; }
    if (v1) v1 += (long)bz * sv1;
    if (v4) v4 += (long)bz * sv4;

    int m0, n0;
    if (tri) {
        int t = blockIdx.x, ti = 0;
        while (t >= 8 - ti) { t -= 8 - ti; ti++; }
        m0 = ti * 128;
        n0 = (ti + t) * 128;
    } else {
        m0 = blockIdx.y * 128;
        n0 = blockIdx.x * 128;
    }
    const int tid = threadIdx.x;
    const int wid = tid >> 5;
    const int lane = tid & 31;
    const int mw = (wid >> 2) * 32;
    const int nw = (wid & 3) * 32;
    const uint32_t sbase = smem_u32(smem);

    float acc[2][4][4];
#pragma unroll
    for (int mt = 0; mt < 2; mt++)
#pragma unroll
        for (int nf = 0; nf < 4; nf++)
#pragma unroll
            for (int q = 0; q < 4; q++) acc[mt][nf][q] = 0.f;

    const int nCh = Kd / 64;
    auto issue = [&](int c) {
        uint32_t sb = sbase + (uint32_t)(c % 3) * STAGE;
        long k0 = (long)c * 64;
        issue_tile(sb + OFF_AH, Ah + (long)m0 * Kd + k0, Kd, tid);
        issue_tile(sb + OFF_AL, Al + (long)m0 * Kd + k0, Kd, tid);
        issue_tile(sb + OFF_BH, Bh + (long)n0 * Kd + k0, Kd, tid);
        issue_tile(sb + OFF_BL, Bl + (long)n0 * Kd + k0, Kd, tid);
        asm volatile("cp.async.commit_group;" ::: "memory");
    };

    issue(0);
    if (nCh > 1) issue(1);
    for (int c = 0; c < nCh; c++) {
        if (c + 2 < nCh) {
            issue(c + 2);
            asm volatile("cp.async.wait_group 2;" ::: "memory");
        } else if (c + 1 < nCh) {
            asm volatile("cp.async.wait_group 1;" ::: "memory");
        } else {
            asm volatile("cp.async.wait_group 0;" ::: "memory");
        }
        __syncthreads();
        const uint32_t sb = sbase + (uint32_t)(c % 3) * STAGE;
        compute_ks(sb, 0, mw, nw, lane, acc);
        compute_ks(sb, 1, mw, nw, lane, acc);
        compute_ks(sb, 2, mw, nw, lane, acc);
        compute_ks(sb, 3, mw, nw, lane, acc);
        __syncthreads();
    }

    // epilogue
    const int r = lane >> 2;
    const int cp = (lane & 3) * 2;
#pragma unroll
    for (int mt = 0; mt < 2; mt++)
#pragma unroll
        for (int rr = 0; rr < 2; rr++) {
            const int m = m0 + mw + mt * 16 + r + rr * 8;
            float pv = 0.f, bkv = 0.f;
            if (mode == 1) { pv = v1[m]; bkv = v3[m]; }
#pragma unroll
            for (int nf = 0; nf < 4; nf++) {
                const int nloc = nf * 8 + cp;
                const int n = n0 + nw + nloc;
                float f0 = alpha * acc[mt][nf][rr * 2 + 0];
                float f1 = alpha * acc[mt][nf][rr * 2 + 1];
                if (mode == 1) {
                    f0 += pv * v2[n + 0] + bkv * (v4[n + 0] + rk * v2[n + 0]);
                    f1 += pv * v2[n + 1] + bkv * (v4[n + 1] + rk * v2[n + 1]);
                } else if (mode == 2) {
                    f0 += v1[n + 0];
                    f1 += v1[n + 1];
                }
                long co = (long)m * Nd + n;
                if (Cf) *(float2*)(Cf + co) = make_float2(f0, f1);
                if (Ch) {
                    float h0, l0, h1, l1;
                    split1(f0, h0, l0);
                    split1(f1, h1, l1);
                    *(uint32_t*)(Ch + co) = pack2(h0, h1);
                    *(uint32_t*)(Cl + co) = pack2(l0, l1);
                }
            }
        }
}

// ===========================================================================
// Launch.
//   P = Wq^T Wk, Q = Wo Wv (batch-independent)
//   G_b = x^T x (upper tiles + mirror) ; R_b = Q G_b ;
//   UT_b = R_b P^T + w2 u2^T + w1(u1 + S u2)^T
//   out_b = SCALE * x UT^T + c_b
//   c_b = SCALE * Wo (Wv (G t1) + bv(p.bq) + r(bk.bq) + S bv(bk.bq)) + bo
// ===========================================================================
extern "C" void kernel_launch(void* const* d_in, const int* in_sizes, int n_in,
                              void* d_out, int out_size)
{
    const float* x  = (const float*)d_in[0];
    const float* Wq = (const float*)d_in[1];
    const float* bq = (const float*)d_in[2];
    const float* Wk = (const float*)d_in[3];
    const float* bk = (const float*)d_in[4];
    const float* Wv = (const float*)d_in[5];
    const float* bv = (const float*)d_in[6];
    const float* Wo = (const float*)d_in[7];
    const float* bo = (const float*)d_in[8];
    float* out = (float*)d_out;

    char* scr = nullptr;
    cudaGetSymbolAddress((void**)&scr, g_scratch);
    auto BF = [&](long off) { return (__nv_bfloat16*)(scr + off); };

    __nv_bfloat16 *xs_h = BF(OFF_XS_H), *xs_l = BF(OFF_XS_L);
    __nv_bfloat16 *xt_h = BF(OFF_XT_H), *xt_l = BF(OFF_XT_L);
    __nv_bfloat16 *wqt_h = BF(OFF_WQT_H), *wqt_l = BF(OFF_WQT_L);
    __nv_bfloat16 *wkt_h = BF(OFF_WKT_H), *wkt_l = BF(OFF_WKT_L);
    __nv_bfloat16 *wvt_h = BF(OFF_WVT_H), *wvt_l = BF(OFF_WVT_L);
    __nv_bfloat16 *wo_h  = BF(OFF_WO_H),  *wo_l  = BF(OFF_WO_L);
    __nv_bfloat16 *P_h = BF(OFF_P_H), *P_l = BF(OFF_P_L);
    __nv_bfloat16 *Q_h = BF(OFF_Q_H), *Q_l = BF(OFF_Q_L);
    __nv_bfloat16 *G_h = BF(OFF_G_H), *G_l = BF(OFF_G_L);
    __nv_bfloat16 *R_h = BF(OFF_R_H), *R_l = BF(OFF_R_L);
    __nv_bfloat16 *UT_h = BF(OFF_UT_H), *UT_l = BF(OFF_UT_L);

    float* vec = (float*)(scr + OFF_VEC);
    float* s    = vec;                 // [B][E]
    float* p    = s    + Bd * Ed;      // [B][E]
    float* r    = p    + Bd * Ed;
    float* u1   = r    + Bd * Ed;
    float* w2   = u1   + Bd * Ed;
    float* t2   = w2   + Bd * Ed;
    float* wvt2 = t2   + Bd * Ed;
    float* d    = wvt2 + Bd * Ed;
    float* cb   = d    + Bd * Ed;      // c_b [B][E]
    float* u2   = cb   + Bd * Ed;      // [E]
    float* w1   = u2   + Ed;
    float* t1   = w1   + Ed;
    float* dp   = t1   + Ed;           // [B]
    float* db   = dp   + Bd;           // [1]

    const long sX = (long)Sd * Ed;     // 2M elems, x / xs / out stride
    const long sXT = (long)Ed * Sd;    // xT stride
    const long sEE = (long)Ed * Ed;    // 1M elems

    cudaFuncSetAttribute(bf_gemm, cudaFuncAttributeMaxDynamicSharedMemorySize, DYN_SMEM);

    // ---- preprocessing: splits + transposed splits ----
    split_k<<<(Bd * sX / 4 + 255) / 256, 256>>>(x, xs_h, xs_l, Bd * sX / 4);
    split_k<<<(sEE / 4 + 255) / 256, 256>>>(Wo, wo_h, wo_l, sEE / 4);
    tsplit_k<<<dim3(Ed / 32, Sd / 32, Bd), dim3(32, 8)>>>(x, sX, xt_h, xt_l, sXT, Sd, Ed);
    tsplit_k<<<dim3(Ed / 32, Ed / 32, 1), dim3(32, 8)>>>(Wq, 0, wqt_h, wqt_l, 0, Ed, Ed);
    tsplit_k<<<dim3(Ed / 32, Ed / 32, 1), dim3(32, 8)>>>(Wk, 0, wkt_h, wkt_l, 0, Ed, Ed);
    tsplit_k<<<dim3(Ed / 32, Ed / 32, 1), dim3(32, 8)>>>(Wv, 0, wvt_h, wvt_l, 0, Ed, Ed);

    // ---- vectors (fp32 exact) ----
    coldot_k<<<dim3(Ed / 256, Bd), 256>>>(x, sX, nullptr, 0, s, Ed, Sd, Ed);        // s = colsum x
    rowdot_pr_k<<<dim3(Ed / 8, Bd, 2), 256>>>(Wk, Wv, s, p, r);                     // p = Wk s, r = Wv s
    coldot_k<<<dim3(Ed / 256, Bd), 256>>>(Wq, 0, p, Ed, u1, Ed, Ed, Ed);            // u1 = Wq^T p
    coldot2_k<<<dim3(Ed / 256, 1, 2), 256>>>(Wq, bk, Wk, bq, u2, t1);               // u2, t1
    rowdot_k<<<dim3(Ed / 8, 1), 256>>>(Wo, bv, 0, nullptr, w1, 0, Ed, 1.f);         // w1 = Wo bv
    rowdot_k<<<dim3(Ed / 8, Bd), 256>>>(Wo, r, Ed, nullptr, w2, Ed, Ed, 1.f);       // w2 = Wo r
    dot2_k<<<Bd + 1, 256>>>(p, bk, bq, dp, db);                                     // dp, db

    // ---- GEMMs ----
    dim3 blk(512);
    // P = Wq^T Wk  : A=WqT, B=WkT
    bf_gemm<<<dim3(8, 8, 1), blk, DYN_SMEM>>>(wqt_h, wqt_l, 0, wkt_h, wkt_l, 0,
        nullptr, 0, P_h, P_l, 0, Ed, Ed, 1.f, 0, 0,
        nullptr, 0, nullptr, nullptr, nullptr, 0, 0.f);
    // Q = Wo Wv   : A=Wo, B=WvT
    bf_gemm<<<dim3(8, 8, 1), blk, DYN_SMEM>>>(wo_h, wo_l, 0, wvt_h, wvt_l, 0,
        nullptr, 0, Q_h, Q_l, 0, Ed, Ed, 1.f, 0, 0,
        nullptr, 0, nullptr, nullptr, nullptr, 0, 0.f);
    // G_b = x^T x : upper-triangle tiles only (tri=1, 36 tiles), K=S
    bf_gemm<<<dim3(36, 1, Bd), blk, DYN_SMEM>>>(xt_h, xt_l, sXT, xt_h, xt_l, sXT,
        nullptr, 0, G_h, G_l, sEE, Ed, Sd, 1.f, 0, 1,
        nullptr, 0, nullptr, nullptr, nullptr, 0, 0.f);
    mirror_k<<<dim3(Ed / 32, Ed / 32, Bd * 2), dim3(32, 8)>>>(G_h, G_l, sEE);

    // t2 = G t1 ; wvt2 = Wv t2 ; d ; cb = SCALE*Wo d + bo
    rowdot_bf2_k<<<dim3(Ed / 8, Bd), 256>>>(G_h, G_l, sEE, t1, t2, Ed, Ed);
    rowdot_k<<<dim3(Ed / 8, Bd), 256>>>(Wv, t2, Ed, nullptr, wvt2, Ed, Ed, 1.f);
    vfin_k<<<dim3(Ed / 256, Bd), 256>>>(d, wvt2, bv, r, dp, db);
    rowdot_k<<<dim3(Ed / 8, Bd), 256>>>(Wo, d, Ed, bo, cb, Ed, Ed, SCALE_F);

    // R_b = Q G_b : A=Q (shared), B=G_b (symmetric -> row-major ok)
    bf_gemm<<<dim3(8, 8, Bd), blk, DYN_SMEM>>>(Q_h, Q_l, 0, G_h, G_l, sEE,
        nullptr, 0, R_h, R_l, sEE, Ed, Ed, 1.f, 0, 0,
        nullptr, 0, nullptr, nullptr, nullptr, 0, 0.f);
    // UT_b = R_b P^T + w2 u2^T + w1 (u1 + S u2)^T
    bf_gemm<<<dim3(8, 8, Bd), blk, DYN_SMEM>>>(R_h, R_l, sEE, P_h, P_l, 0,
        nullptr, 0, UT_h, UT_l, sEE, Ed, Ed, 1.f, 1, 0,
        w2, Ed, u2, w1, u1, Ed, (float)Sd);
    // out_b = SCALE * x UT^T + c_b
    bf_gemm<<<dim3(8, 16, Bd), blk, DYN_SMEM>>>(xs_h, xs_l, sX, UT_h, UT_l, sEE,
        out, sX, nullptr, nullptr, 0, Ed, Ed, SCALE_F, 2, 0,
        cb, Ed, nullptr, nullptr, nullptr, 0, 0.f);
}

// round 7
// speedup vs baseline: 4.4454x; 1.2826x over previous
#include <cuda_runtime.h>
#include <cuda_fp16.h>
#include <cstdint>
#include <cstring>

// Problem dims (fixed by setup_inputs)
constexpr int Bd = 4;
constexpr int Sd = 2048;
constexpr int Ed = 1024;
constexpr float SCALE_F = 0.125f;

// ===========================================================================
// scratch layout (bytes) — all split matrices are fp16 hi/lo limb pairs
// ===========================================================================
constexpr long MB = 1024 * 1024;
constexpr long OFF_XS_H = 0;          // x split      [B][S][E]  16MB
constexpr long OFF_XS_L = 16 * MB;
constexpr long OFF_XT_H = 32 * MB;    // x^T split    [B][E][S]  16MB
constexpr long OFF_XT_L = 48 * MB;
constexpr long OFF_WQT_H = 64 * MB;   // Wq^T split   [E][E]      2MB
constexpr long OFF_WQT_L = 66 * MB;
constexpr long OFF_WKT_H = 68 * MB;
constexpr long OFF_WKT_L = 70 * MB;
constexpr long OFF_WVT_H = 72 * MB;
constexpr long OFF_WVT_L = 74 * MB;
constexpr long OFF_WO_H  = 76 * MB;   // Wo split (no transpose)
constexpr long OFF_WO_L  = 78 * MB;
constexpr long OFF_P_H   = 80 * MB;   // P = Wq^T Wk
constexpr long OFF_P_L   = 82 * MB;
constexpr long OFF_Q_H   = 84 * MB;   // Q = Wo Wv
constexpr long OFF_Q_L   = 86 * MB;
constexpr long OFF_G_H   = 88 * MB;   // G  [B][E][E]  8MB
constexpr long OFF_G_L   = 96 * MB;
constexpr long OFF_R_H   = 104 * MB;  // R = Q G
constexpr long OFF_R_L   = 112 * MB;
constexpr long OFF_UT_H  = 120 * MB;  // U^T
constexpr long OFF_UT_L  = 128 * MB;
constexpr long OFF_VEC   = 136 * MB;  // fp32 vectors
constexpr long SCRATCH_BYTES = 138 * MB;

__device__ __align__(1024) char g_scratch[SCRATCH_BYTES];

// ===========================================================================
// helpers
// ===========================================================================
__device__ __forceinline__ uint32_t smem_u32(const void* p) {
    uint32_t a;
    asm("{ .reg .u64 t; cvta.to.shared.u64 t, %1; cvt.u32.u64 %0, t; }" : "=r"(a) : "l"(p));
    return a;
}
#define SWZ128(o) ((o) ^ (((o) >> 3) & 0x70))

__device__ __forceinline__ void split1(float v, float& h, float& l) {
    h = __half2float(__float2half_rn(v));
    l = v - h;
}
__device__ __forceinline__ uint32_t pack2(float a, float b) {
    __half ha = __float2half_rn(a), hb = __float2half_rn(b);
    uint16_t ua, ub;
    memcpy(&ua, &ha, 2); memcpy(&ub, &hb, 2);
    return (uint32_t)ua | ((uint32_t)ub << 16);
}

#define LDMX4(r0, r1, r2, r3, addr)                                            \
    asm volatile("ldmatrix.sync.aligned.m8n8.x4.shared.b16 {%0,%1,%2,%3}, [%4];" \
                 : "=r"(r0), "=r"(r1), "=r"(r2), "=r"(r3) : "r"(addr))

__device__ __forceinline__ void mma16816(float* c, const uint32_t* a, const uint32_t* b) {
    asm volatile(
        "mma.sync.aligned.m16n8k16.row.col.f32.f16.f16.f32 "
        "{%0,%1,%2,%3},{%4,%5,%6,%7},{%8,%9},{%0,%1,%2,%3};"
        : "+f"(c[0]), "+f"(c[1]), "+f"(c[2]), "+f"(c[3])
        : "r"(a[0]), "r"(a[1]), "r"(a[2]), "r"(a[3]), "r"(b[0]), "r"(b[1]));
}
__device__ __forceinline__ void cp16(uint32_t dst, const void* src) {
    asm volatile("cp.async.cg.shared.global [%0], [%1], 16;" :: "r"(dst), "l"(src));
}

// ===========================================================================
// preprocessing: fp32 -> fp16 hi/lo (elementwise + transposed)
// ===========================================================================
__global__ void split_k(const float* __restrict__ in,
                        __half* __restrict__ oh,
                        __half* __restrict__ ol, long n4) {
    long i = (long)blockIdx.x * blockDim.x + threadIdx.x;
    if (i >= n4) return;
    float4 v = ((const float4*)in)[i];
    float h0, l0, h1, l1, h2, l2, h3, l3;
    split1(v.x, h0, l0); split1(v.y, h1, l1);
    split1(v.z, h2, l2); split1(v.w, h3, l3);
    ((uint2*)oh)[i] = make_uint2(pack2(h0, h1), pack2(h2, h3));
    ((uint2*)ol)[i] = make_uint2(pack2(l0, l1), pack2(l2, l3));
}

// in: [R][C] fp32 (batch z, stride sIn elems) -> out: [C][R] fp16 hi/lo
__global__ void tsplit_k(const float* __restrict__ in, long sIn,
                         __half* __restrict__ oh,
                         __half* __restrict__ ol, long sOut,
                         int R, int C) {
    __shared__ float t[32][33];
    in += (long)blockIdx.z * sIn;
    oh += (long)blockIdx.z * sOut;
    ol += (long)blockIdx.z * sOut;
    int c0 = blockIdx.x * 32, r0 = blockIdx.y * 32;
    int tx = threadIdx.x, ty = threadIdx.y;  // (32,8)
#pragma unroll
    for (int i = 0; i < 4; i++)
        t[ty + i * 8][tx] = in[(long)(r0 + ty + i * 8) * C + c0 + tx];
    __syncthreads();
#pragma unroll
    for (int i = 0; i < 4; i++) {
        float v = t[tx][ty + i * 8];
        float h, l;
        split1(v, h, l);
        long o = (long)(c0 + ty + i * 8) * R + r0 + tx;
        oh[o] = __float2half_rn(h);
        ol[o] = __float2half_rn(l);
    }
}

// mirror upper-triangle tiles of symmetric fp16 matrix into lower triangle
__global__ void mirror_k(__half* __restrict__ Gh,
                         __half* __restrict__ Gl, long sEE) {
    int bi = blockIdx.y, bj = blockIdx.x;
    if (bi > bj) return;
    __half* G = ((blockIdx.z & 1) ? Gl : Gh) + (long)(blockIdx.z >> 1) * sEE;
    __shared__ uint16_t t[32][33];
    int tx = threadIdx.x, ty = threadIdx.y;
    int r0 = bi * 32, c0 = bj * 32;
#pragma unroll
    for (int i = 0; i < 4; i++) {
        int r = ty + i * 8;
        uint16_t v;
        memcpy(&v, &G[(long)(r0 + r) * Ed + c0 + tx], 2);
        t[r][tx] = v;
    }
    __syncthreads();
#pragma unroll
    for (int i = 0; i < 4; i++) {
        int rr = ty + i * 8;
        int cc = tx;
        int dr = c0 + rr, dc = r0 + cc;
        if (dr > dc) {
            uint16_t v = t[cc][rr];
            memcpy(&G[(long)dr * Ed + dc], &v, 2);
        }
    }
}

// ===========================================================================
// small vector kernels (fp32)
// ===========================================================================
__global__ void coldot_k(const float* __restrict__ A, long sA,
                         const float* __restrict__ w, long sw,
                         float* __restrict__ y, int sy, int rows, int ldr) {
    A += (long)blockIdx.y * sA;
    if (w) w += (long)blockIdx.y * sw;
    y += blockIdx.y * sy;
    int j = blockIdx.x * blockDim.x + threadIdx.x;
    float acc = 0.f;
#pragma unroll 8
    for (int i = 0; i < rows; i++) {
        float wv = w ? w[i] : 1.f;
        acc += A[(long)i * ldr + j] * wv;
    }
    y[j] = acc;
}

// z=0: y=u2=Wq^T bk ; z=1: y=t1=Wk^T bq
__global__ void coldot2_k(const float* __restrict__ Wq, const float* __restrict__ bk,
                          const float* __restrict__ Wk, const float* __restrict__ bq,
                          float* __restrict__ u2, float* __restrict__ t1) {
    const float* A = blockIdx.z ? Wk : Wq;
    const float* w = blockIdx.z ? bq : bk;
    float* y = blockIdx.z ? t1 : u2;
    int j = blockIdx.x * blockDim.x + threadIdx.x;
    float acc = 0.f;
#pragma unroll 8
    for (int i = 0; i < Ed; i++) acc += A[(long)i * Ed + j] * w[i];
    y[j] = acc;
}

__global__ void rowdot_k(const float* __restrict__ A,
                         const float* __restrict__ xv, int sxv,
                         const float* __restrict__ bias,
                         float* __restrict__ y, int sy, int cols, float alpha) {
    xv += blockIdx.y * sxv;
    y  += blockIdx.y * sy;
    int warp = blockIdx.x * (blockDim.x >> 5) + (threadIdx.x >> 5);
    int lane = threadIdx.x & 31;
    const float* row = A + (long)warp * cols;
    float acc = 0.f;
    for (int j = lane; j < cols; j += 32) acc += row[j] * xv[j];
#pragma unroll
    for (int o = 16; o > 0; o >>= 1) acc += __shfl_xor_sync(0xffffffffu, acc, o);
    if (lane == 0) y[warp] = alpha * acc + (bias ? bias[warp] : 0.f);
}

// z=0: p_b = Wk s_b ; z=1: r_b = Wv s_b
__global__ void rowdot_pr_k(const float* __restrict__ Wk, const float* __restrict__ Wv,
                            const float* __restrict__ s,
                            float* __restrict__ p, float* __restrict__ r) {
    const float* A = blockIdx.z ? Wv : Wk;
    float* y = (blockIdx.z ? r : p) + blockIdx.y * Ed;
    const float* xv = s + blockIdx.y * Ed;
    int warp = blockIdx.x * 8 + (threadIdx.x >> 5);
    int lane = threadIdx.x & 31;
    const float* row = A + (long)warp * Ed;
    float acc = 0.f;
    for (int j = lane; j < Ed; j += 32) acc += row[j] * xv[j];
#pragma unroll
    for (int o = 16; o > 0; o >>= 1) acc += __shfl_xor_sync(0xffffffffu, acc, o);
    if (lane == 0) y[warp] = acc;
}

// y_b[i] = dot((Ah+Al)[i,:], xv)  over split fp16 matrix (batched)
__global__ void rowdot_hf2_k(const __half* __restrict__ Ah,
                             const __half* __restrict__ Al, long sA,
                             const float* __restrict__ xv,
                             float* __restrict__ y, int sy, int cols) {
    Ah += (long)blockIdx.y * sA;
    Al += (long)blockIdx.y * sA;
    y  += blockIdx.y * sy;
    int warp = blockIdx.x * (blockDim.x >> 5) + (threadIdx.x >> 5);
    int lane = threadIdx.x & 31;
    const __half* rh = Ah + (long)warp * cols;
    const __half* rl = Al + (long)warp * cols;
    float acc = 0.f;
    for (int j = lane; j < cols; j += 32)
        acc += (__half2float(rh[j]) + __half2float(rl[j])) * xv[j];
#pragma unroll
    for (int o = 16; o > 0; o >>= 1) acc += __shfl_xor_sync(0xffffffffu, acc, o);
    if (lane == 0) y[warp] = acc;
}

// blocks 0..Bd-1: dp[b] = p_b . bq ; block Bd: db = bk . bq
__global__ void dot2_k(const float* __restrict__ p, const float* __restrict__ bk,
                       const float* __restrict__ bq,
                       float* __restrict__ dp, float* __restrict__ db) {
    int bid = blockIdx.x;
    const float* a = (bid < Bd) ? p + (long)bid * Ed : bk;
    __shared__ float red[8];
    int tid = threadIdx.x;
    float acc = 0.f;
    for (int j = tid; j < Ed; j += 256) acc += a[j] * bq[j];
#pragma unroll
    for (int o = 16; o > 0; o >>= 1) acc += __shfl_xor_sync(0xffffffffu, acc, o);
    if ((tid & 31) == 0) red[tid >> 5] = acc;
    __syncthreads();
    if (tid < 8) {
        float v = red[tid];
#pragma unroll
        for (int o = 4; o > 0; o >>= 1) v += __shfl_xor_sync(0xffu, v, o);
        if (tid == 0) { if (bid < Bd) dp[bid] = v; else db[0] = v; }
    }
}

// d_b[i] = wvt2_b[i] + bv[i]*(dp[b] + S*db) + r_b[i]*db
__global__ void vfin_k(float* __restrict__ d, const float* __restrict__ wvt2,
                       const float* __restrict__ bv, const float* __restrict__ r,
                       const float* __restrict__ dp, const float* __restrict__ db) {
    int b = blockIdx.y;
    int i = blockIdx.x * 256 + threadIdx.x;
    float dbv = db[0];
    d[(long)b * Ed + i] = wvt2[(long)b * Ed + i]
                        + bv[i] * (dp[b] + (float)Sd * dbv)
                        + r[(long)b * Ed + i] * dbv;
}

// ===========================================================================
// fp16 2-product split GEMM engine
//   C = alpha * A_hi (B_hi + B_lo)^T   (A truncation error ~2^-12)
//   A[m][k] (hi limb only), B[n][k] hi+lo, all fp16 K-major
//   512 threads (16 warps, 4x4), warp tile 32x32, block tile 128x128,
//   K-chunk 64, 4-stage cp.async pipeline (48KB/stage), single sync/chunk.
//   mode 1: C += v1[m]*v2[n] + v3[m]*(v4[n] + rk*v2[n])
//   mode 2: C += v1[n]
//   tri: grid.x in [0,36) decodes upper-triangle tile (ti<=tj)
//   dual: blockIdx.z==1 switches to second pointer set (merged P/Q launch)
// ===========================================================================
constexpr int OFF_A  = 0;
constexpr int OFF_BH = 16384;
constexpr int OFF_BL = 32768;
constexpr int STAGE  = 49152;
constexpr int DYN_SMEM = 4 * STAGE;  // 192 KB

__device__ __forceinline__ void issue_tile(uint32_t sdst, const __half* g,
                                           long ldK, int tid) {
#pragma unroll
    for (int i = 0; i < 2; i++) {
        int gi = tid + i * 512;
        int row = gi >> 3, c16 = gi & 7;
        uint32_t off = SWZ128((uint32_t)(row * 128 + c16 * 16));
        cp16(sdst + off, (const char*)(g + (long)row * ldK) + c16 * 16);
    }
}

__device__ __forceinline__ void compute_ks(uint32_t sb, int ks, int mw, int nw,
                                           int lane, float (&acc)[2][4][4]) {
    const uint32_t rowsel = lane & 15;
    const uint32_t ksel = (lane >> 4) * 16;
    uint32_t ah[2][4];
#pragma unroll
    for (int mt = 0; mt < 2; mt++) {
        uint32_t off = SWZ128((uint32_t)((mw + mt * 16 + rowsel) * 128 + ks * 32 + ksel));
        LDMX4(ah[mt][0], ah[mt][1], ah[mt][2], ah[mt][3], sb + OFF_A + off);
    }
    uint32_t bh[4][2], bl[4][2];
#pragma unroll
    for (int nt = 0; nt < 2; nt++) {
        uint32_t off = SWZ128((uint32_t)((nw + nt * 16 + rowsel) * 128 + ks * 32 + ksel));
        uint32_t r0, r1, r2, r3;
        LDMX4(r0, r1, r2, r3, sb + OFF_BH + off);
        bh[2 * nt][0] = r0; bh[2 * nt][1] = r2;
        bh[2 * nt + 1][0] = r1; bh[2 * nt + 1][1] = r3;
        LDMX4(r0, r1, r2, r3, sb + OFF_BL + off);
        bl[2 * nt][0] = r0; bl[2 * nt][1] = r2;
        bl[2 * nt + 1][0] = r1; bl[2 * nt + 1][1] = r3;
    }
#pragma unroll
    for (int mt = 0; mt < 2; mt++)
#pragma unroll
        for (int nf = 0; nf < 4; nf++) {
            mma16816(acc[mt][nf], ah[mt], bh[nf]);  // hi*hi
            mma16816(acc[mt][nf], ah[mt], bl[nf]);  // hi*lo
        }
}

__global__ void __launch_bounds__(512, 1) hf_gemm(
    const __half* __restrict__ Ah, long sA,
    const __half* __restrict__ Bh, const __half* __restrict__ Bl, long sB,
    float* __restrict__ Cf, long sCf,
    __half* __restrict__ Ch, __half* __restrict__ Cl, long sCb,
    int Nd, int Kd, float alpha, int mode, int tri, int dual,
    const __half* __restrict__ A2h, const __half* __restrict__ B2h,
    const __half* __restrict__ B2l, __half* __restrict__ C2h, __half* __restrict__ C2l,
    const float* __restrict__ v1, int sv1, const float* __restrict__ v2,
    const float* __restrict__ v3, const float* __restrict__ v4, int sv4, float rk)
{
    extern __shared__ char smem[];
    const int bz = blockIdx.z;
    if (dual && bz == 1) {
        Ah = A2h; Bh = B2h; Bl = B2l; Ch = C2h; Cl = C2l;
    } else {
        Ah += (long)bz * sA;
        Bh += (long)bz * sB; Bl += (long)bz * sB;
        if (Cf) Cf += (long)bz * sCf;
        if (Ch) { Ch += (long)bz * sCb; Cl += (long)bz * sCb; }
        if (v1) v1 += (long)bz * sv1;
        if (v4) v4 += (long)bz * sv4;
    }

    int m0, n0;
    if (tri) {
        int t = blockIdx.x, ti = 0;
        while (t >= 8 - ti) { t -= 8 - ti; ti++; }
        m0 = ti * 128;
        n0 = (ti + t) * 128;
    } else {
        m0 = blockIdx.y * 128;
        n0 = blockIdx.x * 128;
    }
    const int tid = threadIdx.x;
    const int wid = tid >> 5;
    const int lane = tid & 31;
    const int mw = (wid >> 2) * 32;
    const int nw = (wid & 3) * 32;
    const uint32_t sbase = smem_u32(smem);

    float acc[2][4][4];
#pragma unroll
    for (int mt = 0; mt < 2; mt++)
#pragma unroll
        for (int nf = 0; nf < 4; nf++)
#pragma unroll
            for (int q = 0; q < 4; q++) acc[mt][nf][q] = 0.f;

    const int nCh = Kd / 64;
    auto issue = [&](int c) {
        uint32_t sb = sbase + (uint32_t)(c & 3) * STAGE;
        long k0 = (long)c * 64;
        issue_tile(sb + OFF_A,  Ah + (long)m0 * Kd + k0, Kd, tid);
        issue_tile(sb + OFF_BH, Bh + (long)n0 * Kd + k0, Kd, tid);
        issue_tile(sb + OFF_BL, Bl + (long)n0 * Kd + k0, Kd, tid);
        asm volatile("cp.async.commit_group;" ::: "memory");
    };

    issue(0); issue(1); issue(2);
    for (int c = 0; c < nCh; c++) {
        if (c + 3 <= nCh) {
            asm volatile("cp.async.wait_group 2;" ::: "memory");
        } else if (c + 2 == nCh) {
            asm volatile("cp.async.wait_group 1;" ::: "memory");
        } else {
            asm volatile("cp.async.wait_group 0;" ::: "memory");
        }
        __syncthreads();
        if (c + 3 < nCh) issue(c + 3);
        const uint32_t sb = sbase + (uint32_t)(c & 3) * STAGE;
        compute_ks(sb, 0, mw, nw, lane, acc);
        compute_ks(sb, 1, mw, nw, lane, acc);
        compute_ks(sb, 2, mw, nw, lane, acc);
        compute_ks(sb, 3, mw, nw, lane, acc);
    }
    __syncthreads();

    // epilogue
    const int r = lane >> 2;
    const int cp = (lane & 3) * 2;
#pragma unroll
    for (int mt = 0; mt < 2; mt++)
#pragma unroll
        for (int rr = 0; rr < 2; rr++) {
            const int m = m0 + mw + mt * 16 + r + rr * 8;
            float pv = 0.f, bkv = 0.f;
            if (mode == 1) { pv = v1[m]; bkv = v3[m]; }
#pragma unroll
            for (int nf = 0; nf < 4; nf++) {
                const int nloc = nf * 8 + cp;
                const int n = n0 + nw + nloc;
                float f0 = alpha * acc[mt][nf][rr * 2 + 0];
                float f1 = alpha * acc[mt][nf][rr * 2 + 1];
                if (mode == 1) {
                    f0 += pv * v2[n + 0] + bkv * (v4[n + 0] + rk * v2[n + 0]);
                    f1 += pv * v2[n + 1] + bkv * (v4[n + 1] + rk * v2[n + 1]);
                } else if (mode == 2) {
                    f0 += v1[n + 0];
                    f1 += v1[n + 1];
                }
                long co = (long)m * Nd + n;
                if (Cf) *(float2*)(Cf + co) = make_float2(f0, f1);
                if (Ch) {
                    float h0, l0, h1, l1;
                    split1(f0, h0, l0);
                    split1(f1, h1, l1);
                    *(uint32_t*)(Ch + co) = pack2(h0, h1);
                    *(uint32_t*)(Cl + co) = pack2(l0, l1);
                }
            }
        }
}

// ===========================================================================
// Launch.
//   P = Wq^T Wk, Q = Wo Wv (batch-independent, merged dual launch)
//   G_b = x^T x (upper tiles + mirror) ; R_b = Q G_b ;
//   UT_b = R_b P^T + w2 u2^T + w1(u1 + S u2)^T
//   out_b = SCALE * x UT^T + c_b
//   c_b = SCALE * Wo (Wv (G t1) + bv(p.bq) + r(bk.bq) + S bv(bk.bq)) + bo
// ===========================================================================
extern "C" void kernel_launch(void* const* d_in, const int* in_sizes, int n_in,
                              void* d_out, int out_size)
{
    const float* x  = (const float*)d_in[0];
    const float* Wq = (const float*)d_in[1];
    const float* bq = (const float*)d_in[2];
    const float* Wk = (const float*)d_in[3];
    const float* bk = (const float*)d_in[4];
    const float* Wv = (const float*)d_in[5];
    const float* bv = (const float*)d_in[6];
    const float* Wo = (const float*)d_in[7];
    const float* bo = (const float*)d_in[8];
    float* out = (float*)d_out;

    char* scr = nullptr;
    cudaGetSymbolAddress((void**)&scr, g_scratch);
    auto HF = [&](long off) { return (__half*)(scr + off); };

    __half *xs_h = HF(OFF_XS_H), *xs_l = HF(OFF_XS_L);
    __half *xt_h = HF(OFF_XT_H), *xt_l = HF(OFF_XT_L);
    __half *wqt_h = HF(OFF_WQT_H), *wqt_l = HF(OFF_WQT_L);
    __half *wkt_h = HF(OFF_WKT_H), *wkt_l = HF(OFF_WKT_L);
    __half *wvt_h = HF(OFF_WVT_H), *wvt_l = HF(OFF_WVT_L);
    __half *wo_h  = HF(OFF_WO_H),  *wo_l  = HF(OFF_WO_L);
    __half *P_h = HF(OFF_P_H), *P_l = HF(OFF_P_L);
    __half *Q_h = HF(OFF_Q_H), *Q_l = HF(OFF_Q_L);
    __half *G_h = HF(OFF_G_H), *G_l = HF(OFF_G_L);
    __half *R_h = HF(OFF_R_H), *R_l = HF(OFF_R_L);
    __half *UT_h = HF(OFF_UT_H), *UT_l = HF(OFF_UT_L);

    float* vec = (float*)(scr + OFF_VEC);
    float* s    = vec;                 // [B][E]
    float* p    = s    + Bd * Ed;
    float* r    = p    + Bd * Ed;
    float* u1   = r    + Bd * Ed;
    float* w2   = u1   + Bd * Ed;
    float* t2   = w2   + Bd * Ed;
    float* wvt2 = t2   + Bd * Ed;
    float* d    = wvt2 + Bd * Ed;
    float* cb   = d    + Bd * Ed;
    float* u2   = cb   + Bd * Ed;      // [E]
    float* w1   = u2   + Ed;
    float* t1   = w1   + Ed;
    float* dp   = t1   + Ed;           // [B]
    float* db   = dp   + Bd;           // [1]

    const long sX = (long)Sd * Ed;     // 2M elems
    const long sXT = (long)Ed * Sd;
    const long sEE = (long)Ed * Ed;

    cudaFuncSetAttribute(hf_gemm, cudaFuncAttributeMaxDynamicSharedMemorySize, DYN_SMEM);

    // ---- preprocessing: splits + transposed splits ----
    split_k<<<(Bd * sX / 4 + 255) / 256, 256>>>(x, xs_h, xs_l, Bd * sX / 4);
    split_k<<<(sEE / 4 + 255) / 256, 256>>>(Wo, wo_h, wo_l, sEE / 4);
    tsplit_k<<<dim3(Ed / 32, Sd / 32, Bd), dim3(32, 8)>>>(x, sX, xt_h, xt_l, sXT, Sd, Ed);
    tsplit_k<<<dim3(Ed / 32, Ed / 32, 1), dim3(32, 8)>>>(Wq, 0, wqt_h, wqt_l, 0, Ed, Ed);
    tsplit_k<<<dim3(Ed / 32, Ed / 32, 1), dim3(32, 8)>>>(Wk, 0, wkt_h, wkt_l, 0, Ed, Ed);
    tsplit_k<<<dim3(Ed / 32, Ed / 32, 1), dim3(32, 8)>>>(Wv, 0, wvt_h, wvt_l, 0, Ed, Ed);

    // ---- vectors (fp32 exact) ----
    coldot_k<<<dim3(Ed / 256, Bd), 256>>>(x, sX, nullptr, 0, s, Ed, Sd, Ed);
    rowdot_pr_k<<<dim3(Ed / 8, Bd, 2), 256>>>(Wk, Wv, s, p, r);
    coldot_k<<<dim3(Ed / 256, Bd), 256>>>(Wq, 0, p, Ed, u1, Ed, Ed, Ed);
    coldot2_k<<<dim3(Ed / 256, 1, 2), 256>>>(Wq, bk, Wk, bq, u2, t1);
    rowdot_k<<<dim3(Ed / 8, 1), 256>>>(Wo, bv, 0, nullptr, w1, 0, Ed, 1.f);
    rowdot_k<<<dim3(Ed / 8, Bd), 256>>>(Wo, r, Ed, nullptr, w2, Ed, Ed, 1.f);
    dot2_k<<<Bd + 1, 256>>>(p, bk, bq, dp, db);

    // ---- GEMMs ----
    dim3 blk(512);
    // merged: z=0 -> P = Wq^T Wk ; z=1 -> Q = Wo Wv
    hf_gemm<<<dim3(8, 8, 2), blk, DYN_SMEM>>>(wqt_h, 0, wkt_h, wkt_l, 0,
        nullptr, 0, P_h, P_l, 0, Ed, Ed, 1.f, 0, 0, 1,
        wo_h, wvt_h, wvt_l, Q_h, Q_l,
        nullptr, 0, nullptr, nullptr, nullptr, 0, 0.f);
    // G_b = x^T x : upper-triangle tiles (36) per batch, K=S
    hf_gemm<<<dim3(36, 1, Bd), blk, DYN_SMEM>>>(xt_h, sXT, xt_h, xt_l, sXT,
        nullptr, 0, G_h, G_l, sEE, Ed, Sd, 1.f, 0, 1, 0,
        nullptr, nullptr, nullptr, nullptr, nullptr,
        nullptr, 0, nullptr, nullptr, nullptr, 0, 0.f);
    mirror_k<<<dim3(Ed / 32, Ed / 32, Bd * 2), dim3(32, 8)>>>(G_h, G_l, sEE);

    // t2 = G t1 ; wvt2 = Wv t2 ; d ; cb = SCALE*Wo d + bo
    rowdot_hf2_k<<<dim3(Ed / 8, Bd), 256>>>(G_h, G_l, sEE, t1, t2, Ed, Ed);
    rowdot_k<<<dim3(Ed / 8, Bd), 256>>>(Wv, t2, Ed, nullptr, wvt2, Ed, Ed, 1.f);
    vfin_k<<<dim3(Ed / 256, Bd), 256>>>(d, wvt2, bv, r, dp, db);
    rowdot_k<<<dim3(Ed / 8, Bd), 256>>>(Wo, d, Ed, bo, cb, Ed, Ed, SCALE_F);

    // R_b = Q G_b (G symmetric -> row-major as B ok)
    hf_gemm<<<dim3(8, 8, Bd), blk, DYN_SMEM>>>(Q_h, 0, G_h, G_l, sEE,
        nullptr, 0, R_h, R_l, sEE, Ed, Ed, 1.f, 0, 0, 0,
        nullptr, nullptr, nullptr, nullptr, nullptr,
        nullptr, 0, nullptr, nullptr, nullptr, 0, 0.f);
    // UT_b = R_b P^T + w2 u2^T + w1 (u1 + S u2)^T
    hf_gemm<<<dim3(8, 8, Bd), blk, DYN_SMEM>>>(R_h, sEE, P_h, P_l, 0,
        nullptr, 0, UT_h, UT_l, sEE, Ed, Ed, 1.f, 1, 0, 0,
        nullptr, nullptr, nullptr, nullptr, nullptr,
        w2, Ed, u2, w1, u1, Ed, (float)Sd);
    // out_b = SCALE * x UT^T + c_b
    hf_gemm<<<dim3(8, 16, Bd), blk, DYN_SMEM>>>(xs_h, sX, UT_h, UT_l, sEE,
        out, sX, nullptr, nullptr, 0, Ed, Ed, SCALE_F, 2, 0, 0,
        nullptr, nullptr, nullptr, nullptr, nullptr,
        cb, Ed, nullptr, nullptr, nullptr, 0, 0.f);
}